// round 13
// baseline (speedup 1.0000x reference)
#include <cuda_runtime.h>
#include <cuda_fp16.h>
#include <cstdint>
#include <math.h>

#define NN    50000
#define EE    800000
#define INDIM 300
#define HID   128
#define NL    4
#define LD    640
#define KX    320

#define W_EMB_HI 0
#define W_EMB_LO 40960
#define W_LINL(i) (81920  + (i) * 32768)
#define W_LINR(i) (212992 + (i) * 32768)
#define W_FUS1_HI 344064
#define W_FUS1_LO 425984
#define W_FUS2_HI 507904
#define W_FUS2_LO 524288
#define W_TOTAL   540672

#define STAGE_SZ 24576
#define DSMEM   (1024 + 3 * STAGE_SZ)
#define DSMEM_L (1024 + 16384 + 2 * STAGE_SZ)
#define MAXCH 20

__device__ __align__(256) float   g_REPS[(size_t)NN * LD];
__device__ __align__(256) __half  g_RF  [(size_t)NN * LD];
__device__ __align__(256) __half  g_XF  [(size_t)NN * KX];
__device__ __align__(256) __half  g_TMPF[(size_t)NN * HID];
__device__ __align__(256) __half  g_W   [W_TOTAL];
__device__ float g_invdeg[NN];
__device__ int   g_cnt[NN];
__device__ int   g_cursor[NN];
__device__ int   g_rowptr[NN + 1];
__device__ int   g_col[EE];

struct ChunkTab {
    const __half* A[MAXCH];
    const __half* B[MAXCH];
    int lda[MAXCH];
    int ldb[MAXCH];
    int nk;
};

__device__ __forceinline__ uint32_t smem_u32(const void* p) {
    uint32_t a;
    asm("{ .reg .u64 t; cvta.to.shared.u64 t, %1; cvt.u32.u64 %0, t; }" : "=r"(a) : "l"(p));
    return a;
}
#define SW128(b) ((b) ^ (((b) >> 3) & 0x70))

__device__ __forceinline__ void cp16(uint32_t dst, const void* src, int sz) {
    asm volatile("cp.async.cg.shared.global [%0], [%1], 16, %2;"
                 :: "r"(dst), "l"(src), "r"(sz) : "memory");
}
__device__ __forceinline__ void ldm_x4(uint32_t* r, uint32_t addr) {
    asm volatile("ldmatrix.sync.aligned.m8n8.x4.shared.b16 {%0,%1,%2,%3}, [%4];"
                 : "=r"(r[0]), "=r"(r[1]), "=r"(r[2]), "=r"(r[3]) : "r"(addr));
}
__device__ __forceinline__ void mma_f16(float* c, const uint32_t* a, const uint32_t* b) {
    asm volatile(
        "mma.sync.aligned.m16n8k16.row.col.f32.f16.f16.f32 "
        "{%0,%1,%2,%3}, {%4,%5,%6,%7}, {%8,%9}, {%0,%1,%2,%3};"
        : "+f"(c[0]), "+f"(c[1]), "+f"(c[2]), "+f"(c[3])
        : "r"(a[0]), "r"(a[1]), "r"(a[2]), "r"(a[3]), "r"(b[0]), "r"(b[1]));
}
__device__ __forceinline__ void split2h(float v, __half& hi, __half& lo) {
    hi = __float2half(v);
    lo = __float2half(v - __half2float(hi));
}

__global__ void k_count(const int* __restrict__ dst, int E) {
    int i = blockIdx.x * blockDim.x + threadIdx.x;
    if (i < E) atomicAdd(&g_cnt[dst[i]], 1);
}

__global__ void __launch_bounds__(1024) k_scan(int M) {
    const int T = 1024;
    int t = threadIdx.x;
    int per = (M + T - 1) / T;
    int beg = t * per;
    int end = min(beg + per, M);
    int sum = 0;
    for (int i = beg; i < end; i++) sum += g_cnt[i];

    int lane = t & 31, wid = t >> 5;
    int v = sum;
    #pragma unroll
    for (int o = 1; o < 32; o <<= 1) {
        int u = __shfl_up_sync(0xffffffffu, v, o);
        if (lane >= o) v += u;
    }
    __shared__ int ws[32];
    if (lane == 31) ws[wid] = v;
    __syncthreads();
    if (wid == 0) {
        int wv = ws[lane];
        #pragma unroll
        for (int o = 1; o < 32; o <<= 1) {
            int u = __shfl_up_sync(0xffffffffu, wv, o);
            if (lane >= o) wv += u;
        }
        ws[lane] = wv;
    }
    __syncthreads();
    int run = v - sum + (wid ? ws[wid - 1] : 0);
    for (int i = beg; i < end; i++) {
        int c = g_cnt[i];
        g_rowptr[i] = run;
        g_cursor[i] = run;
        g_invdeg[i] = 1.0f / fmaxf((float)c, 1.0f);
        run += c;
    }
    if (t == T - 1) g_rowptr[M] = run;
}

__global__ void k_fill(const int* __restrict__ src, const int* __restrict__ dst, int E) {
    int i = blockIdx.x * blockDim.x + threadIdx.x;
    if (i < E) {
        int pos = atomicAdd(&g_cursor[dst[i]], 1);
        g_col[pos] = src[i];
    }
}

__device__ __forceinline__ void wsplit_one(const float* W, __half* ohi,
                                           __half* olo, int idx, int K, int Kp) {
    int n = idx / Kp, kp = idx % Kp;
    __half hi, lo;
    if (kp < K) {
        split2h(W[(size_t)kp * 128 + n], hi, lo);
    } else {
        hi = __float2half(0.f); lo = hi;
    }
    ohi[(size_t)n * Kp + kp] = hi;
    olo[(size_t)n * Kp + kp] = lo;
}

__global__ void k_wsplit_all(const float* __restrict__ emb_W,
                             const float* __restrict__ lin_l_W,
                             const float* __restrict__ lin_r_W,
                             const float* __restrict__ fus_W1,
                             const float* __restrict__ fus_W2) {
    int w = blockIdx.x * blockDim.x + threadIdx.x;
    if (w < 40960) {
        wsplit_one(emb_W, g_W + W_EMB_HI, g_W + W_EMB_LO, w, 300, 320);
    } else if (w < 106496) {
        int u = w - 40960, i = u >> 14;
        wsplit_one(lin_l_W + (size_t)i * 16384, g_W + W_LINL(i), g_W + W_LINL(i) + 16384,
                   u & 16383, 128, 128);
    } else if (w < 172032) {
        int u = w - 106496, i = u >> 14;
        wsplit_one(lin_r_W + (size_t)i * 16384, g_W + W_LINR(i), g_W + W_LINR(i) + 16384,
                   u & 16383, 128, 128);
    } else if (w < 253952) {
        wsplit_one(fus_W1, g_W + W_FUS1_HI, g_W + W_FUS1_LO, w - 172032, 640, 640);
    } else if (w < 270336) {
        wsplit_one(fus_W2, g_W + W_FUS2_HI, g_W + W_FUS2_LO, w - 253952, 128, 128);
    }
}

__global__ void k_xcvt(const float* __restrict__ x, int M) {
    int idx = blockIdx.x * blockDim.x + threadIdx.x;
    int row = idx / 80, g = idx % 80;
    if (row >= M) return;
    float vv[4] = {0.f, 0.f, 0.f, 0.f};
    if (g < 75) {
        float4 t = *reinterpret_cast<const float4*>(x + (size_t)row * INDIM + g * 4);
        vv[0] = t.x; vv[1] = t.y; vv[2] = t.z; vv[3] = t.w;
    }
    union { __half h[4]; uint2 u; } p;
    #pragma unroll
    for (int j = 0; j < 4; j++) p.h[j] = __float2half(vv[j]);
    *reinterpret_cast<uint2*>(g_XF + (size_t)row * KX + g * 4) = p.u;
}

__device__ __forceinline__ void agg_row(const __half* __restrict__ H, int row, int lane,
                                        float& a0, float& a1, float& a2, float& a3) {
    int beg = g_rowptr[row], end = g_rowptr[row + 1];
    a0 = a1 = a2 = a3 = 0.f;
    float b0 = 0.f, b1 = 0.f, b2 = 0.f, b3 = 0.f;
    union U { uint2 u; __half2 h2[2]; };
    for (int base = beg; base < end; base += 32) {
        int idx = (base + lane < end) ? g_col[base + lane] : 0;
        int cnt = min(32, end - base);
        int j = 0;
        for (; j + 3 < cnt; j += 4) {
            int s0 = __shfl_sync(0xffffffffu, idx, j);
            int s1 = __shfl_sync(0xffffffffu, idx, j + 1);
            int s2 = __shfl_sync(0xffffffffu, idx, j + 2);
            int s3 = __shfl_sync(0xffffffffu, idx, j + 3);
            U u0, u1, u2, u3;
            u0.u = *reinterpret_cast<const uint2*>(H + (size_t)s0 * LD + lane * 4);
            u1.u = *reinterpret_cast<const uint2*>(H + (size_t)s1 * LD + lane * 4);
            u2.u = *reinterpret_cast<const uint2*>(H + (size_t)s2 * LD + lane * 4);
            u3.u = *reinterpret_cast<const uint2*>(H + (size_t)s3 * LD + lane * 4);
            float2 p;
            p = __half22float2(u0.h2[0]); a0 += p.x; a1 += p.y;
            p = __half22float2(u0.h2[1]); a2 += p.x; a3 += p.y;
            p = __half22float2(u1.h2[0]); b0 += p.x; b1 += p.y;
            p = __half22float2(u1.h2[1]); b2 += p.x; b3 += p.y;
            p = __half22float2(u2.h2[0]); a0 += p.x; a1 += p.y;
            p = __half22float2(u2.h2[1]); a2 += p.x; a3 += p.y;
            p = __half22float2(u3.h2[0]); b0 += p.x; b1 += p.y;
            p = __half22float2(u3.h2[1]); b2 += p.x; b3 += p.y;
        }
        for (; j < cnt; j++) {
            int s = __shfl_sync(0xffffffffu, idx, j);
            U u; u.u = *reinterpret_cast<const uint2*>(H + (size_t)s * LD + lane * 4);
            float2 p;
            p = __half22float2(u.h2[0]); a0 += p.x; a1 += p.y;
            p = __half22float2(u.h2[1]); a2 += p.x; a3 += p.y;
        }
    }
    a0 += b0; a1 += b1; a2 += b2; a3 += b3;
    float w = g_invdeg[row];
    a0 *= w; a1 *= w; a2 *= w; a3 *= w;
}

__device__ __forceinline__ void load_tiles(uint32_t stage, int tid, int m0, int M,
                                           const __half* A, int lda,
                                           const __half* B, int ldb, bool skipA) {
    uint32_t abase = stage;
    uint32_t bbase = stage + 8192u;
    if (!skipA) {
        #pragma unroll
        for (int i = 0; i < 2; i++) {
            int v = tid + i * 256;
            int r = v >> 3, ch = v & 7;
            uint32_t bo = (uint32_t)(r * 128 + ch * 16);
            int row = m0 + r;
            int rc = row < M ? row : 0;
            cp16(abase + SW128(bo), A + (rc * lda + ch * 8), row < M ? 16 : 0);
        }
    }
    #pragma unroll
    for (int i = 0; i < 4; i++) {
        int v = tid + i * 256;
        int r = v >> 3, ch = v & 7;
        uint32_t bo = (uint32_t)(r * 128 + ch * 16);
        cp16(bbase + SW128(bo), B + (r * ldb + ch * 8), 16);
    }
    asm volatile("cp.async.commit_group;" ::: "memory");
}

template <int MODE>
__device__ __forceinline__ void epilogue(char* smem, int wid, int lane, int m0, int M,
                                         const float* bias, const float* lng, const float* lnb,
                                         const float* skip, float* outF, int ldF,
                                         __half* out16, int ldo) {
    float* C = (float*)smem;
    #pragma unroll 1
    for (int t = 0; t < 8; t++) {
        int rr  = wid + t * 8;
        int row = m0 + rr;
        if (row >= M) continue;
        float4 v = *reinterpret_cast<float4*>(C + rr * 132 + lane * 4);
        float4 bb = *reinterpret_cast<const float4*>(bias + lane * 4);
        v.x += bb.x; v.y += bb.y; v.z += bb.z; v.w += bb.w;
        if (MODE == 2) {
            float s  = v.x + v.y + v.z + v.w;
            float ss = v.x * v.x + v.y * v.y + v.z * v.z + v.w * v.w;
            #pragma unroll
            for (int off = 16; off; off >>= 1) {
                s  += __shfl_xor_sync(0xffffffffu, s,  off);
                ss += __shfl_xor_sync(0xffffffffu, ss, off);
            }
            float mu  = s * (1.0f / 128.0f);
            float var = ss * (1.0f / 128.0f) - mu * mu;
            float inv = rsqrtf(var + 1e-5f);
            float4 gg = *reinterpret_cast<const float4*>(lng + lane * 4);
            float4 ob = *reinterpret_cast<const float4*>(lnb + lane * 4);
            v.x = (v.x - mu) * inv * gg.x + ob.x;
            v.y = (v.y - mu) * inv * gg.y + ob.y;
            v.z = (v.z - mu) * inv * gg.z + ob.z;
            v.w = (v.w - mu) * inv * gg.w + ob.w;
            if (skip) {
                float4 sk = *reinterpret_cast<const float4*>(skip + (size_t)row * LD + lane * 4);
                v.x += sk.x; v.y += sk.y; v.z += sk.z; v.w += sk.w;
            }
        }
        if (MODE != 0) {
            v.x = fmaxf(v.x, 0.f); v.y = fmaxf(v.y, 0.f);
            v.z = fmaxf(v.z, 0.f); v.w = fmaxf(v.w, 0.f);
        }
        if (outF) {
            *reinterpret_cast<float4*>(outF + (size_t)row * ldF + lane * 4) = v;
        }
        if (MODE != 0) {
            union { __half h[4]; uint2 u; } p;
            p.h[0] = __float2half(v.x);
            p.h[1] = __float2half(v.y);
            p.h[2] = __float2half(v.z);
            p.h[3] = __float2half(v.w);
            *reinterpret_cast<uint2*>(out16 + (size_t)row * ldo + lane * 4) = p.u;
        }
    }
}

__device__ __forceinline__ void compute_chunk(uint32_t abase, uint32_t bbase,
                                              int wm, int wn, int r_in, int ca8,
                                              int b_na_off, int b_kslice, int brow,
                                              float acc[2][4][4]) {
    #pragma unroll
    for (int ka = 0; ka < 4; ka++) {
        uint32_t a[2][4];
        #pragma unroll
        for (int ma = 0; ma < 2; ma++) {
            int r = wm + ma * 16 + r_in, cc = ka * 16 + ca8;
            ldm_x4(a[ma], abase + SW128((uint32_t)(r * 128 + cc * 2)));
        }
        uint32_t b[2][4];
        #pragma unroll
        for (int na2 = 0; na2 < 2; na2++) {
            int r  = wn + na2 * 16 + b_na_off + brow;
            int cc = ka * 16 + b_kslice;
            ldm_x4(b[na2], bbase + SW128((uint32_t)(r * 128 + cc * 2)));
        }
        #pragma unroll
        for (int ma = 0; ma < 2; ma++)
            #pragma unroll
            for (int na = 0; na < 4; na++)
                mma_f16(acc[ma][na], a[ma], &b[na >> 1][(na & 1) * 2]);
    }
}

__device__ __forceinline__ void park_acc(char* smem, int wm, int wn, int lane,
                                         float acc[2][4][4]) {
    float* C = (float*)smem;
    #pragma unroll
    for (int ma = 0; ma < 2; ma++)
        #pragma unroll
        for (int na = 0; na < 4; na++) {
            int r0 = wm + ma * 16 + (lane >> 2);
            int cc = wn + na * 8 + 2 * (lane & 3);
            C[r0 * 132 + cc]           = acc[ma][na][0];
            C[r0 * 132 + cc + 1]       = acc[ma][na][1];
            C[(r0 + 8) * 132 + cc]     = acc[ma][na][2];
            C[(r0 + 8) * 132 + cc + 1] = acc[ma][na][3];
        }
}

template <int MODE>
__global__ void __launch_bounds__(256, 3)
k_mgemm(ChunkTab ct,
        const float* __restrict__ bias,
        float* __restrict__ outF, int ldF,
        __half* __restrict__ out16, int ldo, int M) {
    extern __shared__ char smem_raw[];
    char* smem = (char*)(((uintptr_t)smem_raw + 1023) & ~(uintptr_t)1023);
    const uint32_t tiles = smem_u32(smem);

    const int tid  = threadIdx.x;
    const int lane = tid & 31, wid = tid >> 5;
    const int m0   = blockIdx.x * 64;

    const int wm = (wid & 1) * 32;
    const int wn = (wid >> 1) * 32;

    float acc[2][4][4];
    #pragma unroll
    for (int i = 0; i < 2; i++)
        #pragma unroll
        for (int j = 0; j < 4; j++)
            #pragma unroll
            for (int q = 0; q < 4; q++) acc[i][j][q] = 0.f;

    const int nk = ct.nk;
    const int r_in = ((lane >> 3) & 1) * 8 + (lane & 7);
    const int ca8  = (lane >> 4) * 8;
    const int bg   = lane >> 3;
    const int brow = lane & 7;
    const int b_na_off  = (bg >> 1) * 8;
    const int b_kslice  = (bg & 1) * 8;

    load_tiles(tiles, tid, m0, M, ct.A[0], ct.lda[0], ct.B[0], ct.ldb[0], false);
    if (nk > 1) load_tiles(tiles + STAGE_SZ, tid, m0, M, ct.A[1], ct.lda[1], ct.B[1], ct.ldb[1], false);

    #pragma unroll 1
    for (int c = 0; c < nk; c++) {
        if (c + 1 < nk) asm volatile("cp.async.wait_group 1;" ::: "memory");
        else            asm volatile("cp.async.wait_group 0;" ::: "memory");
        __syncthreads();
        if (c + 2 < nk) {
            int cn = c + 2;
            load_tiles(tiles + (uint32_t)(cn % 3) * STAGE_SZ, tid, m0, M,
                       ct.A[cn], ct.lda[cn], ct.B[cn], ct.ldb[cn], false);
        }
        uint32_t abase = tiles + (uint32_t)(c % 3) * STAGE_SZ;
        compute_chunk(abase, abase + 8192u, wm, wn, r_in, ca8, b_na_off, b_kslice, brow, acc);
    }
    __syncthreads();
    park_acc(smem, wm, wn, lane, acc);
    __syncthreads();
    epilogue<MODE>(smem, wid, lane, m0, M, bias, nullptr, nullptr, nullptr,
                   outF, ldF, out16, ldo);
}

__global__ void __launch_bounds__(256, 3)
k_lgemm(ChunkTab ct, const __half* __restrict__ Hprev,
        const float* __restrict__ bias, const float* __restrict__ lng, const float* __restrict__ lnb,
        const float* __restrict__ skip, float* __restrict__ outF, int ldF,
        __half* __restrict__ out16, int ldo, int M) {
    extern __shared__ char smem_raw[];
    char* smem = (char*)(((uintptr_t)smem_raw + 1023) & ~(uintptr_t)1023);
    const uint32_t aggbuf = smem_u32(smem);
    const uint32_t stg    = aggbuf + 16384u;

    const int tid  = threadIdx.x;
    const int lane = tid & 31, wid = tid >> 5;
    const int m0   = blockIdx.x * 64;

    // agg prologue: 8 warps x 8 rows -> aggbuf (SW128 fp16, 2 chunk-tiles of 64 cols)
    #pragma unroll 1
    for (int t = 0; t < 8; t++) {
        int r = wid * 8 + t;
        int row = m0 + r;
        float a0 = 0.f, a1 = 0.f, a2 = 0.f, a3 = 0.f;
        if (row < M) agg_row(Hprev, row, lane, a0, a1, a2, a3);
        union { __half h[4]; uint2 u; } p;
        p.h[0] = __float2half(a0); p.h[1] = __float2half(a1);
        p.h[2] = __float2half(a2); p.h[3] = __float2half(a3);
        int colb = lane * 4;
        *reinterpret_cast<uint2*>(smem + (uint32_t)((colb >> 6) * 8192)
                                  + SW128((uint32_t)(r * 128 + (colb & 63) * 2))) = p.u;
    }
    __syncthreads();

    const int wm = (wid & 1) * 32;
    const int wn = (wid >> 1) * 32;
    const int r_in = ((lane >> 3) & 1) * 8 + (lane & 7);
    const int ca8  = (lane >> 4) * 8;
    const int bg   = lane >> 3;
    const int brow = lane & 7;
    const int b_na_off  = (bg >> 1) * 8;
    const int b_kslice  = (bg & 1) * 8;

    float acc[2][4][4];
    #pragma unroll
    for (int i = 0; i < 2; i++)
        #pragma unroll
        for (int j = 0; j < 4; j++)
            #pragma unroll
            for (int q = 0; q < 4; q++) acc[i][j][q] = 0.f;

    const int nk = 8;
    load_tiles(stg, tid, m0, M, ct.A[0], ct.lda[0], ct.B[0], ct.ldb[0], false);

    #pragma unroll 1
    for (int c = 0; c < nk; c++) {
        if (c + 1 < nk) {
            int cn = c + 1;
            load_tiles(stg + (uint32_t)(cn & 1) * STAGE_SZ, tid, m0, M,
                       ct.A[cn], ct.lda[cn], ct.B[cn], ct.ldb[cn], cn >= 4);
            asm volatile("cp.async.wait_group 1;" ::: "memory");
        } else {
            asm volatile("cp.async.wait_group 0;" ::: "memory");
        }
        __syncthreads();
        uint32_t abase = (c >= 4) ? (aggbuf + (uint32_t)(((c - 4) & 1) * 8192))
                                  : (stg + (uint32_t)(c & 1) * STAGE_SZ);
        uint32_t bbase = stg + (uint32_t)(c & 1) * STAGE_SZ + 8192u;
        compute_chunk(abase, bbase, wm, wn, r_in, ca8, b_na_off, b_kslice, brow, acc);
        __syncthreads();
    }
    park_acc(smem, wm, wn, lane, acc);
    __syncthreads();
    epilogue<2>(smem, wid, lane, m0, M, bias, lng, lnb, skip, outF, ldF, out16, ldo);
}

static inline void add_seg(ChunkTab& ct, const __half* A, int lda,
                           const __half* B, int ldb, int nch) {
    for (int c = 0; c < nch; c++) {
        ct.A[ct.nk]   = A ? (A + c * 64) : nullptr;
        ct.B[ct.nk]   = B + c * 64;
        ct.lda[ct.nk] = lda;
        ct.ldb[ct.nk] = ldb;
        ct.nk++;
    }
}

extern "C" void kernel_launch(void* const* d_in, const int* in_sizes, int n_in,
                              void* d_out, int out_size) {
    const float* x       = (const float*)d_in[0];
    const int*   ei      = (const int*)  d_in[1];
    const float* emb_W   = (const float*)d_in[2];
    const float* emb_b   = (const float*)d_in[3];
    const float* lin_l_W = (const float*)d_in[4];
    const float* lin_l_b = (const float*)d_in[5];
    const float* lin_r_W = (const float*)d_in[6];
    const float* ln_g    = (const float*)d_in[7];
    const float* ln_b    = (const float*)d_in[8];
    const float* fus_W1  = (const float*)d_in[9];
    const float* fus_b1  = (const float*)d_in[10];
    const float* fus_W2  = (const float*)d_in[11];
    const float* fus_b2  = (const float*)d_in[12];
    float* out = (float*)d_out;

    const int M = in_sizes[0] / INDIM;
    const int E = in_sizes[1] / 2;

    float *REPS; __half *RF, *XF, *TMPF, *W;
    int *CNT;
    cudaGetSymbolAddress((void**)&REPS, g_REPS);
    cudaGetSymbolAddress((void**)&RF,   g_RF);
    cudaGetSymbolAddress((void**)&XF,   g_XF);
    cudaGetSymbolAddress((void**)&TMPF, g_TMPF);
    cudaGetSymbolAddress((void**)&W,    g_W);
    cudaGetSymbolAddress((void**)&CNT,  g_cnt);

    cudaFuncSetAttribute(k_mgemm<0>, cudaFuncAttributeMaxDynamicSharedMemorySize, DSMEM);
    cudaFuncSetAttribute(k_mgemm<1>, cudaFuncAttributeMaxDynamicSharedMemorySize, DSMEM);
    cudaFuncSetAttribute(k_lgemm,    cudaFuncAttributeMaxDynamicSharedMemorySize, DSMEM_L);

    const int* src = ei;
    const int* dst = ei + E;

    const int G = (M + 63) / 64;

    cudaMemsetAsync(CNT, 0, (size_t)M * sizeof(int), 0);
    k_wsplit_all<<<(270336 + 255) / 256, 256>>>(emb_W, lin_l_W, lin_r_W, fus_W1, fus_W2);
    k_count<<<(E + 255) / 256, 256>>>(dst, E);
    k_xcvt<<<((M * 80) + 255) / 256, 256>>>(x, M);

    {
        ChunkTab ct; ct.nk = 0;
        add_seg(ct, XF, KX, W + W_EMB_HI, KX, 5);
        add_seg(ct, XF, KX, W + W_EMB_LO, KX, 5);
        k_mgemm<1><<<G, 256, DSMEM>>>(ct, emb_b, nullptr, 0, RF, LD, M);
    }

    k_scan<<<1, 1024>>>(M);
    k_fill<<<(E + 255) / 256, 256>>>(src, dst, E);

    for (int i = 0; i < NL; i++) {
        ChunkTab ct; ct.nk = 0;
        const __half* LLH = W + W_LINL(i);
        const __half* LLL = LLH + 16384;
        const __half* LRH = W + W_LINR(i);
        const __half* LRL = LRH + 16384;
        const __half* HF  = RF + (size_t)i * HID;
        add_seg(ct, HF, LD, LRH, HID, 2);
        add_seg(ct, HF, LD, LRL, HID, 2);
        add_seg(ct, nullptr, 0, LLH, HID, 2);
        add_seg(ct, nullptr, 0, LLL, HID, 2);
        k_lgemm<<<G, 256, DSMEM_L>>>(ct, HF,
                                     lin_l_b + (size_t)i * HID,
                                     ln_g + (size_t)i * HID, ln_b + (size_t)i * HID,
                                     (i > 0) ? (REPS + (size_t)i * HID) : nullptr,
                                     (i + 1 < NL) ? (REPS + (size_t)(i + 1) * HID) : nullptr, LD,
                                     RF + (size_t)(i + 1) * HID, LD, M);
    }

    {
        ChunkTab ct; ct.nk = 0;
        add_seg(ct, RF, LD, W + W_FUS1_HI, LD, 10);
        add_seg(ct, RF, LD, W + W_FUS1_LO, LD, 10);
        k_mgemm<1><<<G, 256, DSMEM>>>(ct, fus_b1, nullptr, 0, TMPF, HID, M);
    }
    {
        ChunkTab ct; ct.nk = 0;
        add_seg(ct, TMPF, HID, W + W_FUS2_HI, HID, 2);
        add_seg(ct, TMPF, HID, W + W_FUS2_LO, HID, 2);
        k_mgemm<0><<<G, 256, DSMEM>>>(ct, fus_b2, out, HID, nullptr, 0, M);
    }
}

// round 14
// speedup vs baseline: 1.2575x; 1.2575x over previous
#include <cuda_runtime.h>
#include <cuda_fp16.h>
#include <cstdint>
#include <math.h>

#define NN    50000
#define EE    800000
#define INDIM 300
#define HID   128
#define NL    4
#define LD    640
#define KX    320

#define W_EMB_HI 0
#define W_EMB_LO 40960
#define W_LINL(i) (81920  + (i) * 32768)
#define W_LINR(i) (212992 + (i) * 32768)
#define W_FUS1_HI 344064
#define W_FUS1_LO 425984
#define W_FUS2_HI 507904
#define W_FUS2_LO 524288
#define W_TOTAL   540672

#define STAGE_SZ 24576
#define DSMEM (1024 + 3 * STAGE_SZ)
#define MAXCH 20

// ---------------- scratch ----------------
__device__ __align__(256) float   g_REPS[(size_t)NN * LD];   // fp32 skip slices 1..3
__device__ __align__(256) __half  g_RF  [(size_t)NN * LD];   // fp16 activations
__device__ __align__(256) __half  g_XF  [(size_t)NN * KX];
__device__ __align__(256) __half  g_AGGF[(size_t)NN * HID];
__device__ __align__(256) __half  g_TMPF[(size_t)NN * HID];
__device__ __align__(256) __half  g_W   [W_TOTAL];
__device__ float g_invdeg[NN];
__device__ int   g_cnt[NN];
__device__ int   g_cursor[NN];
__device__ int   g_rowptr[NN + 1];
__device__ int   g_col[EE];

struct ChunkTab {
    const __half* A[MAXCH];
    const __half* B[MAXCH];
    int lda[MAXCH];
    int ldb[MAXCH];
    int nk;
};

// ---------------- helpers ----------------
__device__ __forceinline__ uint32_t smem_u32(const void* p) {
    uint32_t a;
    asm("{ .reg .u64 t; cvta.to.shared.u64 t, %1; cvt.u32.u64 %0, t; }" : "=r"(a) : "l"(p));
    return a;
}
#define SW128(b) ((b) ^ (((b) >> 3) & 0x70))

__device__ __forceinline__ void cp16(uint32_t dst, const void* src, int sz) {
    asm volatile("cp.async.cg.shared.global [%0], [%1], 16, %2;"
                 :: "r"(dst), "l"(src), "r"(sz) : "memory");
}
__device__ __forceinline__ void ldm_x4(uint32_t* r, uint32_t addr) {
    asm volatile("ldmatrix.sync.aligned.m8n8.x4.shared.b16 {%0,%1,%2,%3}, [%4];"
                 : "=r"(r[0]), "=r"(r[1]), "=r"(r[2]), "=r"(r[3]) : "r"(addr));
}
__device__ __forceinline__ void mma_f16(float* c, const uint32_t* a, const uint32_t* b) {
    asm volatile(
        "mma.sync.aligned.m16n8k16.row.col.f32.f16.f16.f32 "
        "{%0,%1,%2,%3}, {%4,%5,%6,%7}, {%8,%9}, {%0,%1,%2,%3};"
        : "+f"(c[0]), "+f"(c[1]), "+f"(c[2]), "+f"(c[3])
        : "r"(a[0]), "r"(a[1]), "r"(a[2]), "r"(a[3]), "r"(b[0]), "r"(b[1]));
}
__device__ __forceinline__ void split2h(float v, __half& hi, __half& lo) {
    hi = __float2half(v);
    lo = __float2half(v - __half2float(hi));
}

// ---------------- CSR build ----------------
__global__ void k_count(const int* __restrict__ dst, int E) {
    int i = blockIdx.x * blockDim.x + threadIdx.x;
    if (i < E) atomicAdd(&g_cnt[dst[i]], 1);
}

__global__ void __launch_bounds__(1024) k_scan(int M) {
    const int T = 1024;
    int t = threadIdx.x;
    int per = (M + T - 1) / T;
    int beg = t * per;
    int end = min(beg + per, M);
    int sum = 0;
    for (int i = beg; i < end; i++) sum += g_cnt[i];

    int lane = t & 31, wid = t >> 5;
    int v = sum;
    #pragma unroll
    for (int o = 1; o < 32; o <<= 1) {
        int u = __shfl_up_sync(0xffffffffu, v, o);
        if (lane >= o) v += u;
    }
    __shared__ int ws[32];
    if (lane == 31) ws[wid] = v;
    __syncthreads();
    if (wid == 0) {
        int wv = ws[lane];
        #pragma unroll
        for (int o = 1; o < 32; o <<= 1) {
            int u = __shfl_up_sync(0xffffffffu, wv, o);
            if (lane >= o) wv += u;
        }
        ws[lane] = wv;
    }
    __syncthreads();
    int run = v - sum + (wid ? ws[wid - 1] : 0);
    for (int i = beg; i < end; i++) {
        int c = g_cnt[i];
        g_rowptr[i] = run;
        g_cursor[i] = run;
        g_invdeg[i] = 1.0f / fmaxf((float)c, 1.0f);
        run += c;
    }
    if (t == T - 1) g_rowptr[M] = run;
}

__global__ void k_fill(const int* __restrict__ src, const int* __restrict__ dst, int E) {
    int i = blockIdx.x * blockDim.x + threadIdx.x;
    if (i < E) {
        int pos = atomicAdd(&g_cursor[dst[i]], 1);
        g_col[pos] = src[i];
    }
}

// ---------------- weight prep ----------------
__device__ __forceinline__ void wsplit_one(const float* W, __half* ohi,
                                           __half* olo, int idx, int K, int Kp) {
    int n = idx / Kp, kp = idx % Kp;
    __half hi, lo;
    if (kp < K) {
        split2h(W[(size_t)kp * 128 + n], hi, lo);
    } else {
        hi = __float2half(0.f); lo = hi;
    }
    ohi[(size_t)n * Kp + kp] = hi;
    olo[(size_t)n * Kp + kp] = lo;
}

__global__ void k_wsplit_all(const float* __restrict__ emb_W,
                             const float* __restrict__ lin_l_W,
                             const float* __restrict__ lin_r_W,
                             const float* __restrict__ fus_W1,
                             const float* __restrict__ fus_W2) {
    int w = blockIdx.x * blockDim.x + threadIdx.x;
    if (w < 40960) {
        wsplit_one(emb_W, g_W + W_EMB_HI, g_W + W_EMB_LO, w, 300, 320);
    } else if (w < 106496) {
        int u = w - 40960, i = u >> 14;
        wsplit_one(lin_l_W + (size_t)i * 16384, g_W + W_LINL(i), g_W + W_LINL(i) + 16384,
                   u & 16383, 128, 128);
    } else if (w < 172032) {
        int u = w - 106496, i = u >> 14;
        wsplit_one(lin_r_W + (size_t)i * 16384, g_W + W_LINR(i), g_W + W_LINR(i) + 16384,
                   u & 16383, 128, 128);
    } else if (w < 253952) {
        wsplit_one(fus_W1, g_W + W_FUS1_HI, g_W + W_FUS1_LO, w - 172032, 640, 640);
    } else if (w < 270336) {
        wsplit_one(fus_W2, g_W + W_FUS2_HI, g_W + W_FUS2_LO, w - 253952, 128, 128);
    }
}

__global__ void k_xcvt(const float* __restrict__ x, int M) {
    int idx = blockIdx.x * blockDim.x + threadIdx.x;
    int row = idx / 80, g = idx % 80;
    if (row >= M) return;
    float vv[4] = {0.f, 0.f, 0.f, 0.f};
    if (g < 75) {
        float4 t = *reinterpret_cast<const float4*>(x + (size_t)row * INDIM + g * 4);
        vv[0] = t.x; vv[1] = t.y; vv[2] = t.z; vv[3] = t.w;
    }
    union { __half h[4]; uint2 u; } p;
    #pragma unroll
    for (int j = 0; j < 4; j++) p.h[j] = __float2half(vv[j]);
    *reinterpret_cast<uint2*>(g_XF + (size_t)row * KX + g * 4) = p.u;
}

// ---------------- mean aggregation from fp16 rows -> fp16 ----------------
__global__ void k_agg(const __half* __restrict__ H /* RF slice, ld=LD */, int M) {
    int gw   = (blockIdx.x * blockDim.x + threadIdx.x) >> 5;
    int lane = threadIdx.x & 31;
    if (gw >= M) return;
    int beg = g_rowptr[gw], end = g_rowptr[gw + 1];
    float a0 = 0.f, a1 = 0.f, a2 = 0.f, a3 = 0.f;
    float b0 = 0.f, b1 = 0.f, b2 = 0.f, b3 = 0.f;
    union U { uint2 u; __half2 h2[2]; };
    for (int base = beg; base < end; base += 32) {
        int idx = (base + lane < end) ? g_col[base + lane] : 0;
        int cnt = min(32, end - base);
        int j = 0;
        for (; j + 3 < cnt; j += 4) {
            int s0 = __shfl_sync(0xffffffffu, idx, j);
            int s1 = __shfl_sync(0xffffffffu, idx, j + 1);
            int s2 = __shfl_sync(0xffffffffu, idx, j + 2);
            int s3 = __shfl_sync(0xffffffffu, idx, j + 3);
            U u0, u1, u2, u3;
            u0.u = *reinterpret_cast<const uint2*>(H + (size_t)s0 * LD + lane * 4);
            u1.u = *reinterpret_cast<const uint2*>(H + (size_t)s1 * LD + lane * 4);
            u2.u = *reinterpret_cast<const uint2*>(H + (size_t)s2 * LD + lane * 4);
            u3.u = *reinterpret_cast<const uint2*>(H + (size_t)s3 * LD + lane * 4);
            float2 p;
            p = __half22float2(u0.h2[0]); a0 += p.x; a1 += p.y;
            p = __half22float2(u0.h2[1]); a2 += p.x; a3 += p.y;
            p = __half22float2(u1.h2[0]); b0 += p.x; b1 += p.y;
            p = __half22float2(u1.h2[1]); b2 += p.x; b3 += p.y;
            p = __half22float2(u2.h2[0]); a0 += p.x; a1 += p.y;
            p = __half22float2(u2.h2[1]); a2 += p.x; a3 += p.y;
            p = __half22float2(u3.h2[0]); b0 += p.x; b1 += p.y;
            p = __half22float2(u3.h2[1]); b2 += p.x; b3 += p.y;
        }
        for (; j < cnt; j++) {
            int s = __shfl_sync(0xffffffffu, idx, j);
            U u; u.u = *reinterpret_cast<const uint2*>(H + (size_t)s * LD + lane * 4);
            float2 p;
            p = __half22float2(u.h2[0]); a0 += p.x; a1 += p.y;
            p = __half22float2(u.h2[1]); a2 += p.x; a3 += p.y;
        }
    }
    a0 += b0; a1 += b1; a2 += b2; a3 += b3;
    float w = g_invdeg[gw];
    union { __half h[4]; uint2 u; } p;
    p.h[0] = __float2half(a0 * w);
    p.h[1] = __float2half(a1 * w);
    p.h[2] = __float2half(a2 * w);
    p.h[3] = __float2half(a3 * w);
    *reinterpret_cast<uint2*>(g_AGGF + (size_t)gw * HID + lane * 4) = p.u;
}

// ---------------- tile loader ----------------
__device__ __forceinline__ void load_tiles(uint32_t tiles, int s, int tid, int m0, int M,
                                           const __half* A, int lda,
                                           const __half* B, int ldb) {
    uint32_t abase = tiles + (uint32_t)s * STAGE_SZ;
    uint32_t bbase = abase + 8192u;
    #pragma unroll
    for (int i = 0; i < 2; i++) {
        int v = tid + i * 256;
        int r = v >> 3, ch = v & 7;
        uint32_t bo = (uint32_t)(r * 128 + ch * 16);
        int row = m0 + r;
        int rc = row < M ? row : 0;
        cp16(abase + SW128(bo), A + (rc * lda + ch * 8), row < M ? 16 : 0);
    }
    #pragma unroll
    for (int i = 0; i < 4; i++) {
        int v = tid + i * 256;
        int r = v >> 3, ch = v & 7;
        uint32_t bo = (uint32_t)(r * 128 + ch * 16);
        cp16(bbase + SW128(bo), B + (r * ldb + ch * 8), 16);
    }
    asm volatile("cp.async.commit_group;" ::: "memory");
}

// ---------------- mma.sync GEMM, 64x128 tile, BK=64, 3-stage, chunk table ----------------
// MODE 0: C + bias                              -> outF
// MODE 1: relu(C + bias)                        -> [outF] + out16
// MODE 2: LN(C + bias)*g+b (+skip), relu        -> [outF] + out16
template <int MODE>
__global__ void __launch_bounds__(256, 3)
k_mgemm(ChunkTab ct,
        const float* __restrict__ bias, const float* __restrict__ lng, const float* __restrict__ lnb,
        const float* __restrict__ skip, float* __restrict__ outF, int ldF,
        __half* __restrict__ out16, int ldo, int M) {
    extern __shared__ char smem_raw[];
    char* smem = (char*)(((uintptr_t)smem_raw + 1023) & ~(uintptr_t)1023);
    const uint32_t tiles = smem_u32(smem);

    const int tid  = threadIdx.x;
    const int lane = tid & 31, wid = tid >> 5;
    const int m0   = blockIdx.x * 64;

    const int wm = (wid & 1) * 32;
    const int wn = (wid >> 1) * 32;

    float acc[2][4][4];
    #pragma unroll
    for (int i = 0; i < 2; i++)
        #pragma unroll
        for (int j = 0; j < 4; j++)
            #pragma unroll
            for (int q = 0; q < 4; q++) acc[i][j][q] = 0.f;

    const int nk = ct.nk;

    const int r_in = ((lane >> 3) & 1) * 8 + (lane & 7);
    const int ca8  = (lane >> 4) * 8;
    const int bg   = lane >> 3;
    const int brow = lane & 7;
    const int b_na_off  = (bg >> 1) * 8;
    const int b_kslice  = (bg & 1) * 8;

    load_tiles(tiles, 0, tid, m0, M, ct.A[0], ct.lda[0], ct.B[0], ct.ldb[0]);
    if (nk > 1) load_tiles(tiles, 1, tid, m0, M, ct.A[1], ct.lda[1], ct.B[1], ct.ldb[1]);

    #pragma unroll 1
    for (int c = 0; c < nk; c++) {
        if (c + 1 < nk) asm volatile("cp.async.wait_group 1;" ::: "memory");
        else            asm volatile("cp.async.wait_group 0;" ::: "memory");
        __syncthreads();
        if (c + 2 < nk) {
            int cn = c + 2;
            load_tiles(tiles, cn % 3, tid, m0, M, ct.A[cn], ct.lda[cn], ct.B[cn], ct.ldb[cn]);
        }

        uint32_t abase = tiles + (uint32_t)(c % 3) * STAGE_SZ;
        uint32_t bbase = abase + 8192u;
        #pragma unroll
        for (int ka = 0; ka < 4; ka++) {
            uint32_t a[2][4];
            #pragma unroll
            for (int ma = 0; ma < 2; ma++) {
                int r = wm + ma * 16 + r_in, cc = ka * 16 + ca8;
                ldm_x4(a[ma], abase + SW128((uint32_t)(r * 128 + cc * 2)));
            }
            uint32_t b[2][4];
            #pragma unroll
            for (int na2 = 0; na2 < 2; na2++) {
                int r  = wn + na2 * 16 + b_na_off + brow;
                int cc = ka * 16 + b_kslice;
                ldm_x4(b[na2], bbase + SW128((uint32_t)(r * 128 + cc * 2)));
            }
            #pragma unroll
            for (int ma = 0; ma < 2; ma++)
                #pragma unroll
                for (int na = 0; na < 4; na++)
                    mma_f16(acc[ma][na], a[ma], &b[na >> 1][(na & 1) * 2]);
        }
    }
    __syncthreads();

    // park accumulators in smem C [64][132] fp32
    float* C = (float*)smem;
    #pragma unroll
    for (int ma = 0; ma < 2; ma++)
        #pragma unroll
        for (int na = 0; na < 4; na++) {
            int r0 = wm + ma * 16 + (lane >> 2);
            int cc = wn + na * 8 + 2 * (lane & 3);
            C[r0 * 132 + cc]           = acc[ma][na][0];
            C[r0 * 132 + cc + 1]       = acc[ma][na][1];
            C[(r0 + 8) * 132 + cc]     = acc[ma][na][2];
            C[(r0 + 8) * 132 + cc + 1] = acc[ma][na][3];
        }
    __syncthreads();

    // epilogue: warp per row (8 rows per warp)
    #pragma unroll 1
    for (int t = 0; t < 8; t++) {
        int rr  = wid + t * 8;
        int row = m0 + rr;
        if (row >= M) continue;
        float4 v = *reinterpret_cast<float4*>(C + rr * 132 + lane * 4);
        float4 bb = *reinterpret_cast<const float4*>(bias + lane * 4);
        v.x += bb.x; v.y += bb.y; v.z += bb.z; v.w += bb.w;
        if (MODE == 2) {
            float s  = v.x + v.y + v.z + v.w;
            float ss = v.x * v.x + v.y * v.y + v.z * v.z + v.w * v.w;
            #pragma unroll
            for (int off = 16; off; off >>= 1) {
                s  += __shfl_xor_sync(0xffffffffu, s,  off);
                ss += __shfl_xor_sync(0xffffffffu, ss, off);
            }
            float mu  = s * (1.0f / 128.0f);
            float var = ss * (1.0f / 128.0f) - mu * mu;
            float inv = rsqrtf(var + 1e-5f);
            float4 gg = *reinterpret_cast<const float4*>(lng + lane * 4);
            float4 ob = *reinterpret_cast<const float4*>(lnb + lane * 4);
            v.x = (v.x - mu) * inv * gg.x + ob.x;
            v.y = (v.y - mu) * inv * gg.y + ob.y;
            v.z = (v.z - mu) * inv * gg.z + ob.z;
            v.w = (v.w - mu) * inv * gg.w + ob.w;
            if (skip) {
                float4 sk = *reinterpret_cast<const float4*>(skip + (size_t)row * LD + lane * 4);
                v.x += sk.x; v.y += sk.y; v.z += sk.z; v.w += sk.w;
            }
        }
        if (MODE != 0) {
            v.x = fmaxf(v.x, 0.f); v.y = fmaxf(v.y, 0.f);
            v.z = fmaxf(v.z, 0.f); v.w = fmaxf(v.w, 0.f);
        }
        if (outF) {
            *reinterpret_cast<float4*>(outF + (size_t)row * ldF + lane * 4) = v;
        }
        if (MODE != 0) {
            union { __half h[4]; uint2 u; } p;
            p.h[0] = __float2half(v.x);
            p.h[1] = __float2half(v.y);
            p.h[2] = __float2half(v.z);
            p.h[3] = __float2half(v.w);
            *reinterpret_cast<uint2*>(out16 + (size_t)row * ldo + lane * 4) = p.u;
        }
    }
}

// host-side chunk table builder
static inline void add_seg(ChunkTab& ct, const __half* A, int lda,
                           const __half* B, int ldb, int nch) {
    for (int c = 0; c < nch; c++) {
        ct.A[ct.nk]   = A + c * 64;
        ct.B[ct.nk]   = B + c * 64;
        ct.lda[ct.nk] = lda;
        ct.ldb[ct.nk] = ldb;
        ct.nk++;
    }
}

// ---------------- launch ----------------
extern "C" void kernel_launch(void* const* d_in, const int* in_sizes, int n_in,
                              void* d_out, int out_size) {
    const float* x       = (const float*)d_in[0];
    const int*   ei      = (const int*)  d_in[1];
    const float* emb_W   = (const float*)d_in[2];
    const float* emb_b   = (const float*)d_in[3];
    const float* lin_l_W = (const float*)d_in[4];
    const float* lin_l_b = (const float*)d_in[5];
    const float* lin_r_W = (const float*)d_in[6];
    const float* ln_g    = (const float*)d_in[7];
    const float* ln_b    = (const float*)d_in[8];
    const float* fus_W1  = (const float*)d_in[9];
    const float* fus_b1  = (const float*)d_in[10];
    const float* fus_W2  = (const float*)d_in[11];
    const float* fus_b2  = (const float*)d_in[12];
    float* out = (float*)d_out;

    const int M = in_sizes[0] / INDIM;
    const int E = in_sizes[1] / 2;

    float *REPS; __half *RF, *XF, *AGGF, *TMPF, *W;
    int *CNT;
    cudaGetSymbolAddress((void**)&REPS, g_REPS);
    cudaGetSymbolAddress((void**)&RF,   g_RF);
    cudaGetSymbolAddress((void**)&XF,   g_XF);
    cudaGetSymbolAddress((void**)&AGGF, g_AGGF);
    cudaGetSymbolAddress((void**)&TMPF, g_TMPF);
    cudaGetSymbolAddress((void**)&W,    g_W);
    cudaGetSymbolAddress((void**)&CNT,  g_cnt);

    cudaFuncSetAttribute(k_mgemm<0>, cudaFuncAttributeMaxDynamicSharedMemorySize, DSMEM);
    cudaFuncSetAttribute(k_mgemm<1>, cudaFuncAttributeMaxDynamicSharedMemorySize, DSMEM);
    cudaFuncSetAttribute(k_mgemm<2>, cudaFuncAttributeMaxDynamicSharedMemorySize, DSMEM);

    const int* src = ei;
    const int* dst = ei + E;

    const int G = (M + 63) / 64;
    const int warp_grid = (M + 7) / 8;

    // ---- prep + CSR ----
    cudaMemsetAsync(CNT, 0, (size_t)M * sizeof(int), 0);
    k_wsplit_all<<<(270336 + 255) / 256, 256>>>(emb_W, lin_l_W, lin_r_W, fus_W1, fus_W2);
    k_count<<<(E + 255) / 256, 256>>>(dst, E);
    k_xcvt<<<((M * 80) + 255) / 256, 256>>>(x, M);

    // ---- embedding (exact weights: hi+lo) ----
    {
        ChunkTab ct; ct.nk = 0;
        add_seg(ct, XF, KX, W + W_EMB_HI, KX, 5);
        add_seg(ct, XF, KX, W + W_EMB_LO, KX, 5);
        k_mgemm<1><<<G, 256, DSMEM>>>(ct, emb_b, nullptr, nullptr, nullptr,
                                      nullptr, 0, RF, LD, M);
    }

    k_scan<<<1, 1024>>>(M);
    k_fill<<<(E + 255) / 256, 256>>>(src, dst, E);

    // ---- layers (hi-only weights: half the MACs) ----
    for (int i = 0; i < NL; i++) {
        k_agg<<<warp_grid, 256>>>(RF + (size_t)i * HID, M);
        ChunkTab ct; ct.nk = 0;
        const __half* LLH = W + W_LINL(i);
        const __half* LRH = W + W_LINR(i);
        const __half* HF  = RF + (size_t)i * HID;
        add_seg(ct, AGGF, HID, LLH, HID, 2);
        add_seg(ct, HF,   LD,  LRH, HID, 2);
        k_mgemm<2><<<G, 256, DSMEM>>>(ct, lin_l_b + (size_t)i * HID,
                                      ln_g + (size_t)i * HID, ln_b + (size_t)i * HID,
                                      (i > 0) ? (REPS + (size_t)i * HID) : nullptr,
                                      (i + 1 < NL) ? (REPS + (size_t)(i + 1) * HID) : nullptr, LD,
                                      RF + (size_t)(i + 1) * HID, LD, M);
    }

    // ---- fusion MLP: fus1 hi-only, fus2 exact (hi+lo) ----
    {
        ChunkTab ct; ct.nk = 0;
        add_seg(ct, RF, LD, W + W_FUS1_HI, LD, 10);
        k_mgemm<1><<<G, 256, DSMEM>>>(ct, fus_b1, nullptr, nullptr, nullptr,
                                      nullptr, 0, TMPF, HID, M);
    }
    {
        ChunkTab ct; ct.nk = 0;
        add_seg(ct, TMPF, HID, W + W_FUS2_HI, HID, 2);
        add_seg(ct, TMPF, HID, W + W_FUS2_LO, HID, 2);
        k_mgemm<0><<<G, 256, DSMEM>>>(ct, fus_b2, nullptr, nullptr, nullptr,
                                      out, HID, nullptr, 0, M);
    }
}

// round 15
// speedup vs baseline: 1.4856x; 1.1814x over previous
#include <cuda_runtime.h>
#include <cuda_fp16.h>
#include <cstdint>
#include <math.h>

#define NN    50000
#define EE    800000
#define INDIM 300
#define HID   128
#define NL    4
#define LD    640
#define KX    320

#define W_EMB_HI 0
#define W_EMB_LO 40960
#define W_LINL(i) (81920  + (i) * 32768)
#define W_LINR(i) (212992 + (i) * 32768)
#define W_FUS1_HI 344064
#define W_FUS1_LO 425984
#define W_FUS2_HI 507904
#define W_FUS2_LO 524288
#define W_TOTAL   540672

#define STAGE_SZ 24576
#define DSMEM (1024 + 3 * STAGE_SZ)
#define MAXCH 20

// ---------------- scratch ----------------
__device__ __align__(256) __half  g_RF  [(size_t)NN * LD];   // fp16 activations (GEMM A + agg + skip)
__device__ __align__(256) __half  g_XF  [(size_t)NN * KX];
__device__ __align__(256) __half  g_AGGF[(size_t)NN * HID];
__device__ __align__(256) __half  g_TMPF[(size_t)NN * HID];
__device__ __align__(256) __half  g_W   [W_TOTAL];
__device__ float g_invdeg[NN];
__device__ int   g_cnt[NN];
__device__ int   g_cursor[NN];
__device__ int   g_rowptr[NN + 1];
__device__ int   g_col[EE];

struct ChunkTab {
    const __half* A[MAXCH];
    const __half* B[MAXCH];
    int lda[MAXCH];
    int ldb[MAXCH];
    int nk;
};

// ---------------- helpers ----------------
__device__ __forceinline__ uint32_t smem_u32(const void* p) {
    uint32_t a;
    asm("{ .reg .u64 t; cvta.to.shared.u64 t, %1; cvt.u32.u64 %0, t; }" : "=r"(a) : "l"(p));
    return a;
}
#define SW128(b) ((b) ^ (((b) >> 3) & 0x70))

__device__ __forceinline__ void cp16(uint32_t dst, const void* src, int sz) {
    asm volatile("cp.async.cg.shared.global [%0], [%1], 16, %2;"
                 :: "r"(dst), "l"(src), "r"(sz) : "memory");
}
__device__ __forceinline__ void ldm_x4(uint32_t* r, uint32_t addr) {
    asm volatile("ldmatrix.sync.aligned.m8n8.x4.shared.b16 {%0,%1,%2,%3}, [%4];"
                 : "=r"(r[0]), "=r"(r[1]), "=r"(r[2]), "=r"(r[3]) : "r"(addr));
}
__device__ __forceinline__ void mma_f16(float* c, const uint32_t* a, const uint32_t* b) {
    asm volatile(
        "mma.sync.aligned.m16n8k16.row.col.f32.f16.f16.f32 "
        "{%0,%1,%2,%3}, {%4,%5,%6,%7}, {%8,%9}, {%0,%1,%2,%3};"
        : "+f"(c[0]), "+f"(c[1]), "+f"(c[2]), "+f"(c[3])
        : "r"(a[0]), "r"(a[1]), "r"(a[2]), "r"(a[3]), "r"(b[0]), "r"(b[1]));
}
__device__ __forceinline__ void split2h(float v, __half& hi, __half& lo) {
    hi = __float2half(v);
    lo = __float2half(v - __half2float(hi));
}

// ---------------- CSR build ----------------
__global__ void k_count(const int* __restrict__ dst, int E) {
    int i = blockIdx.x * blockDim.x + threadIdx.x;
    if (i < E) atomicAdd(&g_cnt[dst[i]], 1);
}

__global__ void __launch_bounds__(1024) k_scan(int M) {
    const int T = 1024;
    int t = threadIdx.x;
    int per = (M + T - 1) / T;
    int beg = t * per;
    int end = min(beg + per, M);
    int sum = 0;
    for (int i = beg; i < end; i++) sum += g_cnt[i];

    int lane = t & 31, wid = t >> 5;
    int v = sum;
    #pragma unroll
    for (int o = 1; o < 32; o <<= 1) {
        int u = __shfl_up_sync(0xffffffffu, v, o);
        if (lane >= o) v += u;
    }
    __shared__ int ws[32];
    if (lane == 31) ws[wid] = v;
    __syncthreads();
    if (wid == 0) {
        int wv = ws[lane];
        #pragma unroll
        for (int o = 1; o < 32; o <<= 1) {
            int u = __shfl_up_sync(0xffffffffu, wv, o);
            if (lane >= o) wv += u;
        }
        ws[lane] = wv;
    }
    __syncthreads();
    int run = v - sum + (wid ? ws[wid - 1] : 0);
    for (int i = beg; i < end; i++) {
        int c = g_cnt[i];
        g_rowptr[i] = run;
        g_cursor[i] = run;
        g_invdeg[i] = 1.0f / fmaxf((float)c, 1.0f);
        run += c;
    }
    if (t == T - 1) g_rowptr[M] = run;
}

__global__ void k_fill(const int* __restrict__ src, const int* __restrict__ dst, int E) {
    int i = blockIdx.x * blockDim.x + threadIdx.x;
    if (i < E) {
        int pos = atomicAdd(&g_cursor[dst[i]], 1);
        g_col[pos] = src[i];
    }
}

// ---------------- weight prep ----------------
__device__ __forceinline__ void wsplit_one(const float* W, __half* ohi,
                                           __half* olo, int idx, int K, int Kp) {
    int n = idx / Kp, kp = idx % Kp;
    __half hi, lo;
    if (kp < K) {
        split2h(W[(size_t)kp * 128 + n], hi, lo);
    } else {
        hi = __float2half(0.f); lo = hi;
    }
    ohi[(size_t)n * Kp + kp] = hi;
    olo[(size_t)n * Kp + kp] = lo;
}

__global__ void k_wsplit_all(const float* __restrict__ emb_W,
                             const float* __restrict__ lin_l_W,
                             const float* __restrict__ lin_r_W,
                             const float* __restrict__ fus_W1,
                             const float* __restrict__ fus_W2) {
    int w = blockIdx.x * blockDim.x + threadIdx.x;
    if (w < 40960) {
        wsplit_one(emb_W, g_W + W_EMB_HI, g_W + W_EMB_LO, w, 300, 320);
    } else if (w < 106496) {
        int u = w - 40960, i = u >> 14;
        wsplit_one(lin_l_W + (size_t)i * 16384, g_W + W_LINL(i), g_W + W_LINL(i) + 16384,
                   u & 16383, 128, 128);
    } else if (w < 172032) {
        int u = w - 106496, i = u >> 14;
        wsplit_one(lin_r_W + (size_t)i * 16384, g_W + W_LINR(i), g_W + W_LINR(i) + 16384,
                   u & 16383, 128, 128);
    } else if (w < 253952) {
        wsplit_one(fus_W1, g_W + W_FUS1_HI, g_W + W_FUS1_LO, w - 172032, 640, 640);
    } else if (w < 270336) {
        wsplit_one(fus_W2, g_W + W_FUS2_HI, g_W + W_FUS2_LO, w - 253952, 128, 128);
    }
}

__global__ void k_xcvt(const float* __restrict__ x, int M) {
    int idx = blockIdx.x * blockDim.x + threadIdx.x;
    int row = idx / 80, g = idx % 80;
    if (row >= M) return;
    float vv[4] = {0.f, 0.f, 0.f, 0.f};
    if (g < 75) {
        float4 t = *reinterpret_cast<const float4*>(x + (size_t)row * INDIM + g * 4);
        vv[0] = t.x; vv[1] = t.y; vv[2] = t.z; vv[3] = t.w;
    }
    union { __half h[4]; uint2 u; } p;
    #pragma unroll
    for (int j = 0; j < 4; j++) p.h[j] = __float2half(vv[j]);
    *reinterpret_cast<uint2*>(g_XF + (size_t)row * KX + g * 4) = p.u;
}

// ---------------- mean aggregation from fp16 rows -> fp16 ----------------
__global__ void k_agg(const __half* __restrict__ H /* RF slice, ld=LD */, int M) {
    int gw   = (blockIdx.x * blockDim.x + threadIdx.x) >> 5;
    int lane = threadIdx.x & 31;
    if (gw >= M) return;
    int beg = g_rowptr[gw], end = g_rowptr[gw + 1];
    float a0 = 0.f, a1 = 0.f, a2 = 0.f, a3 = 0.f;
    float b0 = 0.f, b1 = 0.f, b2 = 0.f, b3 = 0.f;
    union U { uint2 u; __half2 h2[2]; };
    for (int base = beg; base < end; base += 32) {
        int idx = (base + lane < end) ? g_col[base + lane] : 0;
        int cnt = min(32, end - base);
        int j = 0;
        for (; j + 3 < cnt; j += 4) {
            int s0 = __shfl_sync(0xffffffffu, idx, j);
            int s1 = __shfl_sync(0xffffffffu, idx, j + 1);
            int s2 = __shfl_sync(0xffffffffu, idx, j + 2);
            int s3 = __shfl_sync(0xffffffffu, idx, j + 3);
            U u0, u1, u2, u3;
            u0.u = *reinterpret_cast<const uint2*>(H + (size_t)s0 * LD + lane * 4);
            u1.u = *reinterpret_cast<const uint2*>(H + (size_t)s1 * LD + lane * 4);
            u2.u = *reinterpret_cast<const uint2*>(H + (size_t)s2 * LD + lane * 4);
            u3.u = *reinterpret_cast<const uint2*>(H + (size_t)s3 * LD + lane * 4);
            float2 p;
            p = __half22float2(u0.h2[0]); a0 += p.x; a1 += p.y;
            p = __half22float2(u0.h2[1]); a2 += p.x; a3 += p.y;
            p = __half22float2(u1.h2[0]); b0 += p.x; b1 += p.y;
            p = __half22float2(u1.h2[1]); b2 += p.x; b3 += p.y;
            p = __half22float2(u2.h2[0]); a0 += p.x; a1 += p.y;
            p = __half22float2(u2.h2[1]); a2 += p.x; a3 += p.y;
            p = __half22float2(u3.h2[0]); b0 += p.x; b1 += p.y;
            p = __half22float2(u3.h2[1]); b2 += p.x; b3 += p.y;
        }
        for (; j < cnt; j++) {
            int s = __shfl_sync(0xffffffffu, idx, j);
            U u; u.u = *reinterpret_cast<const uint2*>(H + (size_t)s * LD + lane * 4);
            float2 p;
            p = __half22float2(u.h2[0]); a0 += p.x; a1 += p.y;
            p = __half22float2(u.h2[1]); a2 += p.x; a3 += p.y;
        }
    }
    a0 += b0; a1 += b1; a2 += b2; a3 += b3;
    float w = g_invdeg[gw];
    union { __half h[4]; uint2 u; } p;
    p.h[0] = __float2half(a0 * w);
    p.h[1] = __float2half(a1 * w);
    p.h[2] = __float2half(a2 * w);
    p.h[3] = __float2half(a3 * w);
    *reinterpret_cast<uint2*>(g_AGGF + (size_t)gw * HID + lane * 4) = p.u;
}

// ---------------- tile loader ----------------
__device__ __forceinline__ void load_tiles(uint32_t tiles, int s, int tid, int m0, int M,
                                           const __half* A, int lda,
                                           const __half* B, int ldb) {
    uint32_t abase = tiles + (uint32_t)s * STAGE_SZ;
    uint32_t bbase = abase + 8192u;
    #pragma unroll
    for (int i = 0; i < 2; i++) {
        int v = tid + i * 256;
        int r = v >> 3, ch = v & 7;
        uint32_t bo = (uint32_t)(r * 128 + ch * 16);
        int row = m0 + r;
        int rc = row < M ? row : 0;
        cp16(abase + SW128(bo), A + (rc * lda + ch * 8), row < M ? 16 : 0);
    }
    #pragma unroll
    for (int i = 0; i < 4; i++) {
        int v = tid + i * 256;
        int r = v >> 3, ch = v & 7;
        uint32_t bo = (uint32_t)(r * 128 + ch * 16);
        cp16(bbase + SW128(bo), B + (r * ldb + ch * 8), 16);
    }
    asm volatile("cp.async.commit_group;" ::: "memory");
}

// ---------------- mma.sync GEMM, 64x128 tile, BK=64, 3-stage, chunk table ----------------
// MODE 0: C + bias                              -> outF
// MODE 1: relu(C + bias)                        -> out16
// MODE 2: LN(C + bias)*g+b (+fp16 skip), relu   -> out16
template <int MODE>
__global__ void __launch_bounds__(256, 3)
k_mgemm(ChunkTab ct,
        const float* __restrict__ bias, const float* __restrict__ lng, const float* __restrict__ lnb,
        const __half* __restrict__ skip /* RF slice, ld=LD */,
        float* __restrict__ outF, int ldF,
        __half* __restrict__ out16, int ldo, int M) {
    extern __shared__ char smem_raw[];
    char* smem = (char*)(((uintptr_t)smem_raw + 1023) & ~(uintptr_t)1023);
    const uint32_t tiles = smem_u32(smem);

    const int tid  = threadIdx.x;
    const int lane = tid & 31, wid = tid >> 5;
    const int m0   = blockIdx.x * 64;

    const int wm = (wid & 1) * 32;
    const int wn = (wid >> 1) * 32;

    float acc[2][4][4];
    #pragma unroll
    for (int i = 0; i < 2; i++)
        #pragma unroll
        for (int j = 0; j < 4; j++)
            #pragma unroll
            for (int q = 0; q < 4; q++) acc[i][j][q] = 0.f;

    const int nk = ct.nk;

    const int r_in = ((lane >> 3) & 1) * 8 + (lane & 7);
    const int ca8  = (lane >> 4) * 8;
    const int bg   = lane >> 3;
    const int brow = lane & 7;
    const int b_na_off  = (bg >> 1) * 8;
    const int b_kslice  = (bg & 1) * 8;

    load_tiles(tiles, 0, tid, m0, M, ct.A[0], ct.lda[0], ct.B[0], ct.ldb[0]);
    if (nk > 1) load_tiles(tiles, 1, tid, m0, M, ct.A[1], ct.lda[1], ct.B[1], ct.ldb[1]);

    #pragma unroll 1
    for (int c = 0; c < nk; c++) {
        if (c + 1 < nk) asm volatile("cp.async.wait_group 1;" ::: "memory");
        else            asm volatile("cp.async.wait_group 0;" ::: "memory");
        __syncthreads();
        if (c + 2 < nk) {
            int cn = c + 2;
            load_tiles(tiles, cn % 3, tid, m0, M, ct.A[cn], ct.lda[cn], ct.B[cn], ct.ldb[cn]);
        }

        uint32_t abase = tiles + (uint32_t)(c % 3) * STAGE_SZ;
        uint32_t bbase = abase + 8192u;
        #pragma unroll
        for (int ka = 0; ka < 4; ka++) {
            uint32_t a[2][4];
            #pragma unroll
            for (int ma = 0; ma < 2; ma++) {
                int r = wm + ma * 16 + r_in, cc = ka * 16 + ca8;
                ldm_x4(a[ma], abase + SW128((uint32_t)(r * 128 + cc * 2)));
            }
            uint32_t b[2][4];
            #pragma unroll
            for (int na2 = 0; na2 < 2; na2++) {
                int r  = wn + na2 * 16 + b_na_off + brow;
                int cc = ka * 16 + b_kslice;
                ldm_x4(b[na2], bbase + SW128((uint32_t)(r * 128 + cc * 2)));
            }
            #pragma unroll
            for (int ma = 0; ma < 2; ma++)
                #pragma unroll
                for (int na = 0; na < 4; na++)
                    mma_f16(acc[ma][na], a[ma], &b[na >> 1][(na & 1) * 2]);
        }
    }
    __syncthreads();

    // park accumulators in smem C [64][132] fp32
    float* C = (float*)smem;
    #pragma unroll
    for (int ma = 0; ma < 2; ma++)
        #pragma unroll
        for (int na = 0; na < 4; na++) {
            int r0 = wm + ma * 16 + (lane >> 2);
            int cc = wn + na * 8 + 2 * (lane & 3);
            C[r0 * 132 + cc]           = acc[ma][na][0];
            C[r0 * 132 + cc + 1]       = acc[ma][na][1];
            C[(r0 + 8) * 132 + cc]     = acc[ma][na][2];
            C[(r0 + 8) * 132 + cc + 1] = acc[ma][na][3];
        }
    __syncthreads();

    // epilogue: warp per row (8 rows per warp)
    #pragma unroll 1
    for (int t = 0; t < 8; t++) {
        int rr  = wid + t * 8;
        int row = m0 + rr;
        if (row >= M) continue;
        float4 v = *reinterpret_cast<float4*>(C + rr * 132 + lane * 4);
        float4 bb = *reinterpret_cast<const float4*>(bias + lane * 4);
        v.x += bb.x; v.y += bb.y; v.z += bb.z; v.w += bb.w;
        if (MODE == 2) {
            float s  = v.x + v.y + v.z + v.w;
            float ss = v.x * v.x + v.y * v.y + v.z * v.z + v.w * v.w;
            #pragma unroll
            for (int off = 16; off; off >>= 1) {
                s  += __shfl_xor_sync(0xffffffffu, s,  off);
                ss += __shfl_xor_sync(0xffffffffu, ss, off);
            }
            float mu  = s * (1.0f / 128.0f);
            float var = ss * (1.0f / 128.0f) - mu * mu;
            float inv = rsqrtf(var + 1e-5f);
            float4 gg = *reinterpret_cast<const float4*>(lng + lane * 4);
            float4 ob = *reinterpret_cast<const float4*>(lnb + lane * 4);
            v.x = (v.x - mu) * inv * gg.x + ob.x;
            v.y = (v.y - mu) * inv * gg.y + ob.y;
            v.z = (v.z - mu) * inv * gg.z + ob.z;
            v.w = (v.w - mu) * inv * gg.w + ob.w;
            if (skip) {
                union { uint2 u; __half2 h2[2]; } sk;
                sk.u = *reinterpret_cast<const uint2*>(skip + (size_t)row * LD + lane * 4);
                float2 p0 = __half22float2(sk.h2[0]);
                float2 p1 = __half22float2(sk.h2[1]);
                v.x += p0.x; v.y += p0.y; v.z += p1.x; v.w += p1.y;
            }
        }
        if (MODE != 0) {
            v.x = fmaxf(v.x, 0.f); v.y = fmaxf(v.y, 0.f);
            v.z = fmaxf(v.z, 0.f); v.w = fmaxf(v.w, 0.f);
        }
        if (MODE == 0) {
            *reinterpret_cast<float4*>(outF + (size_t)row * ldF + lane * 4) = v;
        } else {
            union { __half h[4]; uint2 u; } p;
            p.h[0] = __float2half(v.x);
            p.h[1] = __float2half(v.y);
            p.h[2] = __float2half(v.z);
            p.h[3] = __float2half(v.w);
            *reinterpret_cast<uint2*>(out16 + (size_t)row * ldo + lane * 4) = p.u;
        }
    }
}

// host-side chunk table builder
static inline void add_seg(ChunkTab& ct, const __half* A, int lda,
                           const __half* B, int ldb, int nch) {
    for (int c = 0; c < nch; c++) {
        ct.A[ct.nk]   = A + c * 64;
        ct.B[ct.nk]   = B + c * 64;
        ct.lda[ct.nk] = lda;
        ct.ldb[ct.nk] = ldb;
        ct.nk++;
    }
}

// ---------------- launch ----------------
extern "C" void kernel_launch(void* const* d_in, const int* in_sizes, int n_in,
                              void* d_out, int out_size) {
    const float* x       = (const float*)d_in[0];
    const int*   ei      = (const int*)  d_in[1];
    const float* emb_W   = (const float*)d_in[2];
    const float* emb_b   = (const float*)d_in[3];
    const float* lin_l_W = (const float*)d_in[4];
    const float* lin_l_b = (const float*)d_in[5];
    const float* lin_r_W = (const float*)d_in[6];
    const float* ln_g    = (const float*)d_in[7];
    const float* ln_b    = (const float*)d_in[8];
    const float* fus_W1  = (const float*)d_in[9];
    const float* fus_b1  = (const float*)d_in[10];
    const float* fus_W2  = (const float*)d_in[11];
    const float* fus_b2  = (const float*)d_in[12];
    float* out = (float*)d_out;

    const int M = in_sizes[0] / INDIM;
    const int E = in_sizes[1] / 2;

    __half *RF, *XF, *AGGF, *TMPF, *W;
    int *CNT;
    cudaGetSymbolAddress((void**)&RF,   g_RF);
    cudaGetSymbolAddress((void**)&XF,   g_XF);
    cudaGetSymbolAddress((void**)&AGGF, g_AGGF);
    cudaGetSymbolAddress((void**)&TMPF, g_TMPF);
    cudaGetSymbolAddress((void**)&W,    g_W);
    cudaGetSymbolAddress((void**)&CNT,  g_cnt);

    cudaFuncSetAttribute(k_mgemm<0>, cudaFuncAttributeMaxDynamicSharedMemorySize, DSMEM);
    cudaFuncSetAttribute(k_mgemm<1>, cudaFuncAttributeMaxDynamicSharedMemorySize, DSMEM);
    cudaFuncSetAttribute(k_mgemm<2>, cudaFuncAttributeMaxDynamicSharedMemorySize, DSMEM);

    static cudaStream_t s1 = []() {
        cudaStream_t s; cudaStreamCreateWithFlags(&s, cudaStreamNonBlocking); return s;
    }();
    static cudaEvent_t evFork = []() {
        cudaEvent_t e; cudaEventCreateWithFlags(&e, cudaEventDisableTiming); return e;
    }();
    static cudaEvent_t evJoin = []() {
        cudaEvent_t e; cudaEventCreateWithFlags(&e, cudaEventDisableTiming); return e;
    }();

    const int* src = ei;
    const int* dst = ei + E;

    const int G = (M + 63) / 64;
    const int warp_grid = (M + 7) / 8;

    // ---- fork: CSR chain on side stream ----
    cudaEventRecord(evFork, 0);
    cudaStreamWaitEvent(s1, evFork, 0);
    cudaMemsetAsync(CNT, 0, (size_t)M * sizeof(int), s1);
    k_count<<<(E + 255) / 256, 256, 0, s1>>>(dst, E);
    k_scan<<<1, 1024, 0, s1>>>(M);
    k_fill<<<(E + 255) / 256, 256, 0, s1>>>(src, dst, E);
    cudaEventRecord(evJoin, s1);

    // ---- main: prep + embedding ----
    k_wsplit_all<<<(270336 + 255) / 256, 256>>>(emb_W, lin_l_W, lin_r_W, fus_W1, fus_W2);
    k_xcvt<<<((M * 80) + 255) / 256, 256>>>(x, M);
    {
        ChunkTab ct; ct.nk = 0;
        add_seg(ct, XF, KX, W + W_EMB_HI, KX, 5);
        add_seg(ct, XF, KX, W + W_EMB_LO, KX, 5);
        k_mgemm<1><<<G, 256, DSMEM>>>(ct, emb_b, nullptr, nullptr, nullptr,
                                      nullptr, 0, RF, LD, M);
    }
    cudaStreamWaitEvent(0, evJoin, 0);

    // ---- layers (hi-only weights, fp16 skip) ----
    for (int i = 0; i < NL; i++) {
        k_agg<<<warp_grid, 256>>>(RF + (size_t)i * HID, M);
        ChunkTab ct; ct.nk = 0;
        const __half* LLH = W + W_LINL(i);
        const __half* LRH = W + W_LINR(i);
        const __half* HF  = RF + (size_t)i * HID;
        add_seg(ct, AGGF, HID, LLH, HID, 2);
        add_seg(ct, HF,   LD,  LRH, HID, 2);
        k_mgemm<2><<<G, 256, DSMEM>>>(ct, lin_l_b + (size_t)i * HID,
                                      ln_g + (size_t)i * HID, ln_b + (size_t)i * HID,
                                      (i > 0) ? HF : nullptr,
                                      nullptr, 0,
                                      RF + (size_t)(i + 1) * HID, LD, M);
    }

    // ---- fusion MLP: fus1 hi-only, fus2 exact (hi+lo) ----
    {
        ChunkTab ct; ct.nk = 0;
        add_seg(ct, RF, LD, W + W_FUS1_HI, LD, 10);
        k_mgemm<1><<<G, 256, DSMEM>>>(ct, fus_b1, nullptr, nullptr, nullptr,
                                      nullptr, 0, TMPF, HID, M);
    }
    {
        ChunkTab ct; ct.nk = 0;
        add_seg(ct, TMPF, HID, W + W_FUS2_HI, HID, 2);
        add_seg(ct, TMPF, HID, W + W_FUS2_LO, HID, 2);
        k_mgemm<0><<<G, 256, DSMEM>>>(ct, fus_b2, nullptr, nullptr, nullptr,
                                      out, HID, nullptr, 0, M);
    }
}

// round 16
// speedup vs baseline: 1.4981x; 1.0084x over previous
#include <cuda_runtime.h>
#include <cuda_fp16.h>
#include <cstdint>
#include <math.h>

#define NN    50000
#define EE    800000
#define INDIM 300
#define HID   128
#define NL    4
#define LD    640
#define KX    320

#define W_EMB_HI 0
#define W_EMB_LO 40960
#define W_LINL(i) (81920  + (i) * 32768)
#define W_LINR(i) (212992 + (i) * 32768)
#define W_FUS1_HI 344064
#define W_FUS1_LO 425984
#define W_FUS2_HI 507904
#define W_FUS2_LO 524288
#define W_TOTAL   540672

#define STAGE_SZ 24576
#define DSMEM (1024 + 3 * STAGE_SZ)
// fused fusion kernel smem offsets (within aligned base)
#define A2_OFF 34816
#define B2_OFF 51200
#define MAXCH 20

// ---------------- scratch ----------------
__device__ __align__(256) __half  g_RF  [(size_t)NN * LD];   // fp16 activations
__device__ __align__(256) __half  g_XF  [(size_t)NN * KX];
__device__ __align__(256) __half  g_AGGF[(size_t)NN * HID];
__device__ __align__(256) __half  g_W   [W_TOTAL];
__device__ float g_invdeg[NN];
__device__ int   g_cnt[NN];
__device__ int   g_cursor[NN];
__device__ int   g_rowptr[NN + 1];
__device__ int   g_col[EE];

struct ChunkTab {
    const __half* A[MAXCH];
    const __half* B[MAXCH];
    int lda[MAXCH];
    int ldb[MAXCH];
    int nk;
};

// ---------------- helpers ----------------
__device__ __forceinline__ uint32_t smem_u32(const void* p) {
    uint32_t a;
    asm("{ .reg .u64 t; cvta.to.shared.u64 t, %1; cvt.u32.u64 %0, t; }" : "=r"(a) : "l"(p));
    return a;
}
#define SW128(b) ((b) ^ (((b) >> 3) & 0x70))

__device__ __forceinline__ void cp16(uint32_t dst, const void* src, int sz) {
    asm volatile("cp.async.cg.shared.global [%0], [%1], 16, %2;"
                 :: "r"(dst), "l"(src), "r"(sz) : "memory");
}
__device__ __forceinline__ void ldm_x4(uint32_t* r, uint32_t addr) {
    asm volatile("ldmatrix.sync.aligned.m8n8.x4.shared.b16 {%0,%1,%2,%3}, [%4];"
                 : "=r"(r[0]), "=r"(r[1]), "=r"(r[2]), "=r"(r[3]) : "r"(addr));
}
__device__ __forceinline__ void mma_f16(float* c, const uint32_t* a, const uint32_t* b) {
    asm volatile(
        "mma.sync.aligned.m16n8k16.row.col.f32.f16.f16.f32 "
        "{%0,%1,%2,%3}, {%4,%5,%6,%7}, {%8,%9}, {%0,%1,%2,%3};"
        : "+f"(c[0]), "+f"(c[1]), "+f"(c[2]), "+f"(c[3])
        : "r"(a[0]), "r"(a[1]), "r"(a[2]), "r"(a[3]), "r"(b[0]), "r"(b[1]));
}
__device__ __forceinline__ void split2h(float v, __half& hi, __half& lo) {
    hi = __float2half(v);
    lo = __float2half(v - __half2float(hi));
}

// ---------------- CSR build ----------------
__global__ void k_count(const int* __restrict__ dst, int E) {
    int i = blockIdx.x * blockDim.x + threadIdx.x;
    if (i < E) atomicAdd(&g_cnt[dst[i]], 1);
}

__global__ void __launch_bounds__(1024) k_scan(int M) {
    const int T = 1024;
    int t = threadIdx.x;
    int per = (M + T - 1) / T;
    int beg = t * per;
    int end = min(beg + per, M);
    int sum = 0;
    for (int i = beg; i < end; i++) sum += g_cnt[i];

    int lane = t & 31, wid = t >> 5;
    int v = sum;
    #pragma unroll
    for (int o = 1; o < 32; o <<= 1) {
        int u = __shfl_up_sync(0xffffffffu, v, o);
        if (lane >= o) v += u;
    }
    __shared__ int ws[32];
    if (lane == 31) ws[wid] = v;
    __syncthreads();
    if (wid == 0) {
        int wv = ws[lane];
        #pragma unroll
        for (int o = 1; o < 32; o <<= 1) {
            int u = __shfl_up_sync(0xffffffffu, wv, o);
            if (lane >= o) wv += u;
        }
        ws[lane] = wv;
    }
    __syncthreads();
    int run = v - sum + (wid ? ws[wid - 1] : 0);
    for (int i = beg; i < end; i++) {
        int c = g_cnt[i];
        g_rowptr[i] = run;
        g_cursor[i] = run;
        g_invdeg[i] = 1.0f / fmaxf((float)c, 1.0f);
        run += c;
    }
    if (t == T - 1) g_rowptr[M] = run;
}

__global__ void k_fill(const int* __restrict__ src, const int* __restrict__ dst, int E) {
    int i = blockIdx.x * blockDim.x + threadIdx.x;
    if (i < E) {
        int pos = atomicAdd(&g_cursor[dst[i]], 1);
        g_col[pos] = src[i];
    }
}

// ---------------- weight prep ----------------
__device__ __forceinline__ void wsplit_one(const float* W, __half* ohi,
                                           __half* olo, int idx, int K, int Kp) {
    int n = idx / Kp, kp = idx % Kp;
    __half hi, lo;
    if (kp < K) {
        split2h(W[(size_t)kp * 128 + n], hi, lo);
    } else {
        hi = __float2half(0.f); lo = hi;
    }
    ohi[(size_t)n * Kp + kp] = hi;
    if (olo) olo[(size_t)n * Kp + kp] = lo;
}

__global__ void k_wsplit_all(const float* __restrict__ emb_W,
                             const float* __restrict__ lin_l_W,
                             const float* __restrict__ lin_r_W,
                             const float* __restrict__ fus_W1,
                             const float* __restrict__ fus_W2) {
    int w = blockIdx.x * blockDim.x + threadIdx.x;
    if (w < 40960) {
        wsplit_one(emb_W, g_W + W_EMB_HI, nullptr, w, 300, 320);
    } else if (w < 106496) {
        int u = w - 40960, i = u >> 14;
        wsplit_one(lin_l_W + (size_t)i * 16384, g_W + W_LINL(i), nullptr, u & 16383, 128, 128);
    } else if (w < 172032) {
        int u = w - 106496, i = u >> 14;
        wsplit_one(lin_r_W + (size_t)i * 16384, g_W + W_LINR(i), nullptr, u & 16383, 128, 128);
    } else if (w < 253952) {
        wsplit_one(fus_W1, g_W + W_FUS1_HI, nullptr, w - 172032, 640, 640);
    } else if (w < 270336) {
        wsplit_one(fus_W2, g_W + W_FUS2_HI, g_W + W_FUS2_LO, w - 253952, 128, 128);
    }
}

__global__ void k_xcvt(const float* __restrict__ x, int M) {
    int idx = blockIdx.x * blockDim.x + threadIdx.x;
    int row = idx / 80, g = idx % 80;
    if (row >= M) return;
    float vv[4] = {0.f, 0.f, 0.f, 0.f};
    if (g < 75) {
        float4 t = *reinterpret_cast<const float4*>(x + (size_t)row * INDIM + g * 4);
        vv[0] = t.x; vv[1] = t.y; vv[2] = t.z; vv[3] = t.w;
    }
    union { __half h[4]; uint2 u; } p;
    #pragma unroll
    for (int j = 0; j < 4; j++) p.h[j] = __float2half(vv[j]);
    *reinterpret_cast<uint2*>(g_XF + (size_t)row * KX + g * 4) = p.u;
}

// ---------------- mean aggregation from fp16 rows -> fp16 ----------------
__global__ void k_agg(const __half* __restrict__ H, int M) {
    int gw   = (blockIdx.x * blockDim.x + threadIdx.x) >> 5;
    int lane = threadIdx.x & 31;
    if (gw >= M) return;
    int beg = g_rowptr[gw], end = g_rowptr[gw + 1];
    float a0 = 0.f, a1 = 0.f, a2 = 0.f, a3 = 0.f;
    float b0 = 0.f, b1 = 0.f, b2 = 0.f, b3 = 0.f;
    union U { uint2 u; __half2 h2[2]; };
    for (int base = beg; base < end; base += 32) {
        int idx = (base + lane < end) ? g_col[base + lane] : 0;
        int cnt = min(32, end - base);
        int j = 0;
        for (; j + 3 < cnt; j += 4) {
            int s0 = __shfl_sync(0xffffffffu, idx, j);
            int s1 = __shfl_sync(0xffffffffu, idx, j + 1);
            int s2 = __shfl_sync(0xffffffffu, idx, j + 2);
            int s3 = __shfl_sync(0xffffffffu, idx, j + 3);
            U u0, u1, u2, u3;
            u0.u = *reinterpret_cast<const uint2*>(H + (size_t)s0 * LD + lane * 4);
            u1.u = *reinterpret_cast<const uint2*>(H + (size_t)s1 * LD + lane * 4);
            u2.u = *reinterpret_cast<const uint2*>(H + (size_t)s2 * LD + lane * 4);
            u3.u = *reinterpret_cast<const uint2*>(H + (size_t)s3 * LD + lane * 4);
            float2 p;
            p = __half22float2(u0.h2[0]); a0 += p.x; a1 += p.y;
            p = __half22float2(u0.h2[1]); a2 += p.x; a3 += p.y;
            p = __half22float2(u1.h2[0]); b0 += p.x; b1 += p.y;
            p = __half22float2(u1.h2[1]); b2 += p.x; b3 += p.y;
            p = __half22float2(u2.h2[0]); a0 += p.x; a1 += p.y;
            p = __half22float2(u2.h2[1]); a2 += p.x; a3 += p.y;
            p = __half22float2(u3.h2[0]); b0 += p.x; b1 += p.y;
            p = __half22float2(u3.h2[1]); b2 += p.x; b3 += p.y;
        }
        for (; j < cnt; j++) {
            int s = __shfl_sync(0xffffffffu, idx, j);
            U u; u.u = *reinterpret_cast<const uint2*>(H + (size_t)s * LD + lane * 4);
            float2 p;
            p = __half22float2(u.h2[0]); a0 += p.x; a1 += p.y;
            p = __half22float2(u.h2[1]); a2 += p.x; a3 += p.y;
        }
    }
    a0 += b0; a1 += b1; a2 += b2; a3 += b3;
    float w = g_invdeg[gw];
    union { __half h[4]; uint2 u; } p;
    p.h[0] = __float2half(a0 * w);
    p.h[1] = __float2half(a1 * w);
    p.h[2] = __float2half(a2 * w);
    p.h[3] = __float2half(a3 * w);
    *reinterpret_cast<uint2*>(g_AGGF + (size_t)gw * HID + lane * 4) = p.u;
}

// ---------------- tile loaders ----------------
__device__ __forceinline__ void load_tiles(uint32_t tiles, int s, int tid, int m0, int M,
                                           const __half* A, int lda,
                                           const __half* B, int ldb) {
    uint32_t abase = tiles + (uint32_t)s * STAGE_SZ;
    uint32_t bbase = abase + 8192u;
    #pragma unroll
    for (int i = 0; i < 2; i++) {
        int v = tid + i * 256;
        int r = v >> 3, ch = v & 7;
        uint32_t bo = (uint32_t)(r * 128 + ch * 16);
        int row = m0 + r;
        int rc = row < M ? row : 0;
        cp16(abase + SW128(bo), A + (rc * lda + ch * 8), row < M ? 16 : 0);
    }
    #pragma unroll
    for (int i = 0; i < 4; i++) {
        int v = tid + i * 256;
        int r = v >> 3, ch = v & 7;
        uint32_t bo = (uint32_t)(r * 128 + ch * 16);
        cp16(bbase + SW128(bo), B + (r * ldb + ch * 8), 16);
    }
    asm volatile("cp.async.commit_group;" ::: "memory");
}

__device__ __forceinline__ void load_B(uint32_t bbase, int tid, const __half* B, int ldb) {
    #pragma unroll
    for (int i = 0; i < 4; i++) {
        int v = tid + i * 256;
        int r = v >> 3, ch = v & 7;
        uint32_t bo = (uint32_t)(r * 128 + ch * 16);
        cp16(bbase + SW128(bo), B + (r * ldb + ch * 8), 16);
    }
    asm volatile("cp.async.commit_group;" ::: "memory");
}

__device__ __forceinline__ void compute_chunk(uint32_t abase, uint32_t bbase,
                                              int wm, int wn, int r_in, int ca8,
                                              int b_na_off, int b_kslice, int brow,
                                              float acc[2][4][4]) {
    #pragma unroll
    for (int ka = 0; ka < 4; ka++) {
        uint32_t a[2][4];
        #pragma unroll
        for (int ma = 0; ma < 2; ma++) {
            int r = wm + ma * 16 + r_in, cc = ka * 16 + ca8;
            ldm_x4(a[ma], abase + SW128((uint32_t)(r * 128 + cc * 2)));
        }
        uint32_t b[2][4];
        #pragma unroll
        for (int na2 = 0; na2 < 2; na2++) {
            int r  = wn + na2 * 16 + b_na_off + brow;
            int cc = ka * 16 + b_kslice;
            ldm_x4(b[na2], bbase + SW128((uint32_t)(r * 128 + cc * 2)));
        }
        #pragma unroll
        for (int ma = 0; ma < 2; ma++)
            #pragma unroll
            for (int na = 0; na < 4; na++)
                mma_f16(acc[ma][na], a[ma], &b[na >> 1][(na & 1) * 2]);
    }
}

__device__ __forceinline__ void park_acc(char* smem, int wm, int wn, int lane,
                                         float acc[2][4][4]) {
    float* C = (float*)smem;
    #pragma unroll
    for (int ma = 0; ma < 2; ma++)
        #pragma unroll
        for (int na = 0; na < 4; na++) {
            int r0 = wm + ma * 16 + (lane >> 2);
            int cc = wn + na * 8 + 2 * (lane & 3);
            C[r0 * 132 + cc]           = acc[ma][na][0];
            C[r0 * 132 + cc + 1]       = acc[ma][na][1];
            C[(r0 + 8) * 132 + cc]     = acc[ma][na][2];
            C[(r0 + 8) * 132 + cc + 1] = acc[ma][na][3];
        }
}

// ---------------- mma.sync GEMM, 64x128 tile, BK=64, 3-stage ----------------
// MODE 1: relu(C + bias)                        -> out16
// MODE 2: LN(C + bias)*g+b (+fp16 skip), relu   -> out16
template <int MODE>
__global__ void __launch_bounds__(256, 3)
k_mgemm(ChunkTab ct,
        const float* __restrict__ bias, const float* __restrict__ lng, const float* __restrict__ lnb,
        const __half* __restrict__ skip,
        __half* __restrict__ out16, int ldo, int M) {
    extern __shared__ char smem_raw[];
    char* smem = (char*)(((uintptr_t)smem_raw + 1023) & ~(uintptr_t)1023);
    const uint32_t tiles = smem_u32(smem);

    const int tid  = threadIdx.x;
    const int lane = tid & 31, wid = tid >> 5;
    const int m0   = blockIdx.x * 64;

    const int wm = (wid & 1) * 32;
    const int wn = (wid >> 1) * 32;

    float acc[2][4][4];
    #pragma unroll
    for (int i = 0; i < 2; i++)
        #pragma unroll
        for (int j = 0; j < 4; j++)
            #pragma unroll
            for (int q = 0; q < 4; q++) acc[i][j][q] = 0.f;

    const int nk = ct.nk;
    const int r_in = ((lane >> 3) & 1) * 8 + (lane & 7);
    const int ca8  = (lane >> 4) * 8;
    const int bg   = lane >> 3;
    const int brow = lane & 7;
    const int b_na_off  = (bg >> 1) * 8;
    const int b_kslice  = (bg & 1) * 8;

    load_tiles(tiles, 0, tid, m0, M, ct.A[0], ct.lda[0], ct.B[0], ct.ldb[0]);
    if (nk > 1) load_tiles(tiles, 1, tid, m0, M, ct.A[1], ct.lda[1], ct.B[1], ct.ldb[1]);

    #pragma unroll 1
    for (int c = 0; c < nk; c++) {
        if (c + 1 < nk) asm volatile("cp.async.wait_group 1;" ::: "memory");
        else            asm volatile("cp.async.wait_group 0;" ::: "memory");
        __syncthreads();
        if (c + 2 < nk) {
            int cn = c + 2;
            load_tiles(tiles, cn % 3, tid, m0, M, ct.A[cn], ct.lda[cn], ct.B[cn], ct.ldb[cn]);
        }
        uint32_t abase = tiles + (uint32_t)(c % 3) * STAGE_SZ;
        compute_chunk(abase, abase + 8192u, wm, wn, r_in, ca8, b_na_off, b_kslice, brow, acc);
    }
    __syncthreads();
    park_acc(smem, wm, wn, lane, acc);
    __syncthreads();

    float* C = (float*)smem;
    #pragma unroll 1
    for (int t = 0; t < 8; t++) {
        int rr  = wid + t * 8;
        int row = m0 + rr;
        if (row >= M) continue;
        float4 v = *reinterpret_cast<float4*>(C + rr * 132 + lane * 4);
        float4 bb = *reinterpret_cast<const float4*>(bias + lane * 4);
        v.x += bb.x; v.y += bb.y; v.z += bb.z; v.w += bb.w;
        if (MODE == 2) {
            float s  = v.x + v.y + v.z + v.w;
            float ss = v.x * v.x + v.y * v.y + v.z * v.z + v.w * v.w;
            #pragma unroll
            for (int off = 16; off; off >>= 1) {
                s  += __shfl_xor_sync(0xffffffffu, s,  off);
                ss += __shfl_xor_sync(0xffffffffu, ss, off);
            }
            float mu  = s * (1.0f / 128.0f);
            float var = ss * (1.0f / 128.0f) - mu * mu;
            float inv = rsqrtf(var + 1e-5f);
            float4 gg = *reinterpret_cast<const float4*>(lng + lane * 4);
            float4 ob = *reinterpret_cast<const float4*>(lnb + lane * 4);
            v.x = (v.x - mu) * inv * gg.x + ob.x;
            v.y = (v.y - mu) * inv * gg.y + ob.y;
            v.z = (v.z - mu) * inv * gg.z + ob.z;
            v.w = (v.w - mu) * inv * gg.w + ob.w;
            if (skip) {
                union { uint2 u; __half2 h2[2]; } sk;
                sk.u = *reinterpret_cast<const uint2*>(skip + (size_t)row * LD + lane * 4);
                float2 p0 = __half22float2(sk.h2[0]);
                float2 p1 = __half22float2(sk.h2[1]);
                v.x += p0.x; v.y += p0.y; v.z += p1.x; v.w += p1.y;
            }
        }
        v.x = fmaxf(v.x, 0.f); v.y = fmaxf(v.y, 0.f);
        v.z = fmaxf(v.z, 0.f); v.w = fmaxf(v.w, 0.f);
        union { __half h[4]; uint2 u; } p;
        p.h[0] = __float2half(v.x);
        p.h[1] = __float2half(v.y);
        p.h[2] = __float2half(v.z);
        p.h[3] = __float2half(v.w);
        *reinterpret_cast<uint2*>(out16 + (size_t)row * ldo + lane * 4) = p.u;
    }
}

// ---------------- fused fusion: relu(RF@W1+b1) @ W2(+lo) + b2 -> out fp32 ----------------
__global__ void __launch_bounds__(256, 3)
k_fgemm(ChunkTab ct /* 10 fus1 chunks */,
        const float* __restrict__ b1, const float* __restrict__ b2,
        const __half* __restrict__ W2H, const __half* __restrict__ W2L,
        float* __restrict__ out, int M) {
    extern __shared__ char smem_raw[];
    char* smem = (char*)(((uintptr_t)smem_raw + 1023) & ~(uintptr_t)1023);
    const uint32_t base = smem_u32(smem);
    const uint32_t tiles = base;

    const int tid  = threadIdx.x;
    const int lane = tid & 31, wid = tid >> 5;
    const int m0   = blockIdx.x * 64;

    const int wm = (wid & 1) * 32;
    const int wn = (wid >> 1) * 32;

    float acc[2][4][4];
    #pragma unroll
    for (int i = 0; i < 2; i++)
        #pragma unroll
        for (int j = 0; j < 4; j++)
            #pragma unroll
            for (int q = 0; q < 4; q++) acc[i][j][q] = 0.f;

    const int nk = ct.nk;
    const int r_in = ((lane >> 3) & 1) * 8 + (lane & 7);
    const int ca8  = (lane >> 4) * 8;
    const int bg   = lane >> 3;
    const int brow = lane & 7;
    const int b_na_off  = (bg >> 1) * 8;
    const int b_kslice  = (bg & 1) * 8;

    // ---- fus1 mainloop ----
    load_tiles(tiles, 0, tid, m0, M, ct.A[0], ct.lda[0], ct.B[0], ct.ldb[0]);
    if (nk > 1) load_tiles(tiles, 1, tid, m0, M, ct.A[1], ct.lda[1], ct.B[1], ct.ldb[1]);
    #pragma unroll 1
    for (int c = 0; c < nk; c++) {
        if (c + 1 < nk) asm volatile("cp.async.wait_group 1;" ::: "memory");
        else            asm volatile("cp.async.wait_group 0;" ::: "memory");
        __syncthreads();
        if (c + 2 < nk) {
            int cn = c + 2;
            load_tiles(tiles, cn % 3, tid, m0, M, ct.A[cn], ct.lda[cn], ct.B[cn], ct.ldb[cn]);
        }
        uint32_t abase = tiles + (uint32_t)(c % 3) * STAGE_SZ;
        compute_chunk(abase, abase + 8192u, wm, wn, r_in, ca8, b_na_off, b_kslice, brow, acc);
    }
    __syncthreads();
    park_acc(smem, wm, wn, lane, acc);
    __syncthreads();

    // ---- epilogue1: relu(C+b1) -> fp16 A2 region (SW128, 2 chunk tiles) ----
    {
        float* C = (float*)smem;
        #pragma unroll 1
        for (int t = 0; t < 8; t++) {
            int rr = wid + t * 8;
            float4 v = *reinterpret_cast<float4*>(C + rr * 132 + lane * 4);
            float4 bb = *reinterpret_cast<const float4*>(b1 + lane * 4);
            v.x = fmaxf(v.x + bb.x, 0.f);
            v.y = fmaxf(v.y + bb.y, 0.f);
            v.z = fmaxf(v.z + bb.z, 0.f);
            v.w = fmaxf(v.w + bb.w, 0.f);
            union { __half h[4]; uint2 u; } p;
            p.h[0] = __float2half(v.x);
            p.h[1] = __float2half(v.y);
            p.h[2] = __float2half(v.z);
            p.h[3] = __float2half(v.w);
            int colb = lane * 4;
            *reinterpret_cast<uint2*>(smem + A2_OFF + (colb >> 6) * 8192
                                      + SW128((uint32_t)(rr * 128 + (colb & 63) * 2))) = p.u;
        }
    }
    __syncthreads();

    // ---- fus2: 4 chunks (W2H k0/k64, W2L k0/k64), A from A2, single B slot ----
    #pragma unroll
    for (int i = 0; i < 2; i++)
        #pragma unroll
        for (int j = 0; j < 4; j++)
            #pragma unroll
            for (int q = 0; q < 4; q++) acc[i][j][q] = 0.f;

    #pragma unroll 1
    for (int c2 = 0; c2 < 4; c2++) {
        const __half* Wp = (c2 < 2 ? W2H : W2L) + (c2 & 1) * 64;
        load_B(base + B2_OFF, tid, Wp, HID);
        asm volatile("cp.async.wait_group 0;" ::: "memory");
        __syncthreads();
        compute_chunk(base + A2_OFF + (uint32_t)((c2 & 1) * 8192), base + B2_OFF,
                      wm, wn, r_in, ca8, b_na_off, b_kslice, brow, acc);
        __syncthreads();
    }
    park_acc(smem, wm, wn, lane, acc);
    __syncthreads();

    // ---- epilogue2: out = C + b2 (fp32) ----
    {
        float* C = (float*)smem;
        #pragma unroll 1
        for (int t = 0; t < 8; t++) {
            int rr  = wid + t * 8;
            int row = m0 + rr;
            if (row >= M) continue;
            float4 v = *reinterpret_cast<float4*>(C + rr * 132 + lane * 4);
            float4 bb = *reinterpret_cast<const float4*>(b2 + lane * 4);
            v.x += bb.x; v.y += bb.y; v.z += bb.z; v.w += bb.w;
            *reinterpret_cast<float4*>(out + (size_t)row * HID + lane * 4) = v;
        }
    }
}

// host-side chunk table builder
static inline void add_seg(ChunkTab& ct, const __half* A, int lda,
                           const __half* B, int ldb, int nch) {
    for (int c = 0; c < nch; c++) {
        ct.A[ct.nk]   = A + c * 64;
        ct.B[ct.nk]   = B + c * 64;
        ct.lda[ct.nk] = lda;
        ct.ldb[ct.nk] = ldb;
        ct.nk++;
    }
}

// ---------------- launch ----------------
extern "C" void kernel_launch(void* const* d_in, const int* in_sizes, int n_in,
                              void* d_out, int out_size) {
    const float* x       = (const float*)d_in[0];
    const int*   ei      = (const int*)  d_in[1];
    const float* emb_W   = (const float*)d_in[2];
    const float* emb_b   = (const float*)d_in[3];
    const float* lin_l_W = (const float*)d_in[4];
    const float* lin_l_b = (const float*)d_in[5];
    const float* lin_r_W = (const float*)d_in[6];
    const float* ln_g    = (const float*)d_in[7];
    const float* ln_b    = (const float*)d_in[8];
    const float* fus_W1  = (const float*)d_in[9];
    const float* fus_b1  = (const float*)d_in[10];
    const float* fus_W2  = (const float*)d_in[11];
    const float* fus_b2  = (const float*)d_in[12];
    float* out = (float*)d_out;

    const int M = in_sizes[0] / INDIM;
    const int E = in_sizes[1] / 2;

    __half *RF, *XF, *AGGF, *W;
    int *CNT;
    cudaGetSymbolAddress((void**)&RF,   g_RF);
    cudaGetSymbolAddress((void**)&XF,   g_XF);
    cudaGetSymbolAddress((void**)&AGGF, g_AGGF);
    cudaGetSymbolAddress((void**)&W,    g_W);
    cudaGetSymbolAddress((void**)&CNT,  g_cnt);

    cudaFuncSetAttribute(k_mgemm<1>, cudaFuncAttributeMaxDynamicSharedMemorySize, DSMEM);
    cudaFuncSetAttribute(k_mgemm<2>, cudaFuncAttributeMaxDynamicSharedMemorySize, DSMEM);
    cudaFuncSetAttribute(k_fgemm,    cudaFuncAttributeMaxDynamicSharedMemorySize, DSMEM);

    static cudaStream_t s1 = []() {
        cudaStream_t s; cudaStreamCreateWithFlags(&s, cudaStreamNonBlocking); return s;
    }();
    static cudaEvent_t evFork = []() {
        cudaEvent_t e; cudaEventCreateWithFlags(&e, cudaEventDisableTiming); return e;
    }();
    static cudaEvent_t evJoin = []() {
        cudaEvent_t e; cudaEventCreateWithFlags(&e, cudaEventDisableTiming); return e;
    }();

    const int* src = ei;
    const int* dst = ei + E;

    const int G = (M + 63) / 64;
    const int warp_grid = (M + 7) / 8;

    // ---- fork: CSR chain on side stream ----
    cudaEventRecord(evFork, 0);
    cudaStreamWaitEvent(s1, evFork, 0);
    cudaMemsetAsync(CNT, 0, (size_t)M * sizeof(int), s1);
    k_count<<<(E + 255) / 256, 256, 0, s1>>>(dst, E);
    k_scan<<<1, 1024, 0, s1>>>(M);
    k_fill<<<(E + 255) / 256, 256, 0, s1>>>(src, dst, E);
    cudaEventRecord(evJoin, s1);

    // ---- main: prep + embedding (hi-only weights) ----
    k_wsplit_all<<<(270336 + 255) / 256, 256>>>(emb_W, lin_l_W, lin_r_W, fus_W1, fus_W2);
    k_xcvt<<<((M * 80) + 255) / 256, 256>>>(x, M);
    {
        ChunkTab ct; ct.nk = 0;
        add_seg(ct, XF, KX, W + W_EMB_HI, KX, 5);
        k_mgemm<1><<<G, 256, DSMEM>>>(ct, emb_b, nullptr, nullptr, nullptr, RF, LD, M);
    }
    cudaStreamWaitEvent(0, evJoin, 0);

    // ---- layers (hi-only weights, fp16 skip) ----
    for (int i = 0; i < NL; i++) {
        k_agg<<<warp_grid, 256>>>(RF + (size_t)i * HID, M);
        ChunkTab ct; ct.nk = 0;
        const __half* LLH = W + W_LINL(i);
        const __half* LRH = W + W_LINR(i);
        const __half* HF  = RF + (size_t)i * HID;
        add_seg(ct, AGGF, HID, LLH, HID, 2);
        add_seg(ct, HF,   LD,  LRH, HID, 2);
        k_mgemm<2><<<G, 256, DSMEM>>>(ct, lin_l_b + (size_t)i * HID,
                                      ln_g + (size_t)i * HID, ln_b + (size_t)i * HID,
                                      (i > 0) ? HF : nullptr,
                                      RF + (size_t)(i + 1) * HID, LD, M);
    }

    // ---- fused fusion MLP ----
    {
        ChunkTab ct; ct.nk = 0;
        add_seg(ct, RF, LD, W + W_FUS1_HI, LD, 10);
        k_fgemm<<<G, 256, DSMEM>>>(ct, fus_b1, fus_b2,
                                   W + W_FUS2_HI, W + W_FUS2_LO, out, M);
    }
}